// round 9
// baseline (speedup 1.0000x reference)
#include <cuda_runtime.h>
#include <cuda_bf16.h>
#include <math.h>
#include <cstdint>

#define B_  4
#define L_  256
#define D_  256
#define P_  32
#define H_  8
#define HD_ 32
#define DH_ 128   // D/2

// ======================= mma.sync bf16 + ldmatrix ==========================
__device__ __forceinline__ void mma16816(float* c, const unsigned* a, const unsigned* b) {
    asm volatile("mma.sync.aligned.m16n8k16.row.col.f32.bf16.bf16.f32 "
        "{%0,%1,%2,%3}, {%4,%5,%6,%7}, {%8,%9}, {%0,%1,%2,%3};"
        : "+f"(c[0]), "+f"(c[1]), "+f"(c[2]), "+f"(c[3])
        : "r"(a[0]), "r"(a[1]), "r"(a[2]), "r"(a[3]), "r"(b[0]), "r"(b[1]));
}
#define LDMATRIX_X4(R0, R1, R2, R3, ADDR) \
    asm volatile("ldmatrix.sync.aligned.m8n8.x4.shared.b16 {%0,%1,%2,%3}, [%4];" \
        : "=r"(R0), "=r"(R1), "=r"(R2), "=r"(R3) : "r"(ADDR))

__device__ __forceinline__ uint32_t smem_u32(const void* p) {
    uint32_t a;
    asm("{ .reg .u64 t; cvta.to.shared.u64 t, %1; cvt.u32.u64 %0, t; }" : "=r"(a) : "l"(p));
    return a;
}
__device__ __forceinline__ void split2(float x0, float x1, unsigned& whi, unsigned& wlo) {
    __nv_bfloat16 h0 = __float2bfloat16(x0);
    __nv_bfloat16 h1 = __float2bfloat16(x1);
    __nv_bfloat16 l0 = __float2bfloat16(x0 - __bfloat162float(h0));
    __nv_bfloat16 l1 = __float2bfloat16(x1 - __bfloat162float(h1));
    whi = (unsigned)*(unsigned short*)&h0 | ((unsigned)*(unsigned short*)&h1 << 16);
    wlo = (unsigned)*(unsigned short*)&l0 | ((unsigned)*(unsigned short*)&l1 << 16);
}
__device__ __forceinline__ void split1(float x, __nv_bfloat16& h, __nv_bfloat16& l) {
    h = __float2bfloat16(x);
    l = __float2bfloat16(x - __bfloat162float(h));
}

// ======================= scratch =========================================
__device__ __nv_bfloat16 g_kh[B_*L_*D_];
__device__ __nv_bfloat16 g_kl[B_*L_*D_];
__device__ __nv_bfloat16 g_vth[B_*D_*L_];       // [(b*D + c)][l]
__device__ __nv_bfloat16 g_vtl[B_*D_*L_];
__device__ __nv_bfloat16 g_qh[B_*P_*L_*D_];
__device__ __nv_bfloat16 g_ql[B_*P_*L_*D_];
__device__ __nv_bfloat16 g_ctxh[B_*P_*L_*D_];
__device__ __nv_bfloat16 g_ctxl[B_*P_*L_*D_];
__device__ __nv_bfloat16 g_hh[B_*P_*L_*DH_];
__device__ __nv_bfloat16 g_hl[B_*P_*L_*DH_];
__device__ __nv_bfloat16 g_woTh[D_*D_];         // [n][k]
__device__ __nv_bfloat16 g_woTl[D_*D_];
__device__ __nv_bfloat16 g_w2qTh[D_*DH_];       // [n][k], scale folded
__device__ __nv_bfloat16 g_w2qTl[D_*DH_];
__device__ float g_W2q[DH_*D_];
__device__ float g_bq2[D_];                     // scale folded

// ---------------------------------------------------------------------------
// Kernel 1: W2q = w2 @ wq, bq2 = scale*(b2 @ wq + bq)
// ---------------------------------------------------------------------------
__global__ void fuse_w_kernel(const float* __restrict__ w2, const float* __restrict__ wq,
                              const float* __restrict__ b2, const float* __restrict__ bq) {
    int j = blockIdx.x, c = threadIdx.x;
    float acc = 0.f;
    for (int k = 0; k < D_; k++) acc = fmaf(w2[j*D_+k], wq[k*D_+c], acc);
    g_W2q[j*D_+c] = acc;
    if (j == 0) {
        float a = 0.f;
        for (int k = 0; k < D_; k++) a = fmaf(b2[k], wq[k*D_+c], a);
        g_bq2[c] = 0.17677669529663687f * (a + bq[c]);
    }
}

// ---------------------------------------------------------------------------
// Kernel 1b: transpose+split wo and scale*W2q
// ---------------------------------------------------------------------------
__global__ void prep_split_kernel(const float* __restrict__ wo) {
    int n = blockIdx.x, k = threadIdx.x;
    __nv_bfloat16 h, l;
    split1(wo[k*D_ + n], h, l);
    g_woTh[n*D_ + k] = h;
    g_woTl[n*D_ + k] = l;
    if (k < DH_) {
        split1(0.17677669529663687f * g_W2q[k*D_ + n], h, l);
        g_w2qTh[n*DH_ + k] = h;
        g_w2qTl[n*DH_ + k] = l;
    }
}

// ---------------------------------------------------------------------------
// Kernel 2: k/v projections, emitted as bf16 hi/lo (K row-major, V transposed)
// ---------------------------------------------------------------------------
__global__ void kv_kernel(const float* __restrict__ ehr,
                          const float* __restrict__ wk, const float* __restrict__ bk,
                          const float* __restrict__ wv, const float* __restrict__ bv) {
    __shared__ float sx[8*D_];
    int row0 = blockIdx.x * 8;
    int tid = threadIdx.x;
    for (int i = tid; i < 8*D_; i += 256) sx[i] = ehr[row0*D_ + i];
    __syncthreads();
    int c = tid;
    float ak[8], av[8];
    float bkc = bk[c], bvc = bv[c];
#pragma unroll
    for (int r = 0; r < 8; r++) { ak[r] = bkc; av[r] = bvc; }
    for (int d = 0; d < D_; d++) {
        float wkd = wk[d*D_+c];
        float wvd = wv[d*D_+c];
#pragma unroll
        for (int r = 0; r < 8; r++) {
            float x = sx[r*D_+d];
            ak[r] = fmaf(x, wkd, ak[r]);
            av[r] = fmaf(x, wvd, av[r]);
        }
    }
#pragma unroll
    for (int r = 0; r < 8; r++) {
        __nv_bfloat16 h, l;
        split1(ak[r], h, l);
        g_kh[(row0+r)*D_+c] = h;
        g_kl[(row0+r)*D_+c] = l;
    }
    {
        int b  = row0 / L_;
        int l0 = row0 % L_;
        __nv_bfloat16 vh8[8], vl8[8];
#pragma unroll
        for (int r = 0; r < 8; r++) split1(av[r], vh8[r], vl8[r]);
        *(uint4*)&g_vth[(b*D_ + c)*L_ + l0] = *(uint4*)vh8;
        *(uint4*)&g_vtl[(b*D_ + c)*L_ + l0] = *(uint4*)vl8;
    }
}

// ---------------------------------------------------------------------------
// Kernel 3: time features -> MLP -> gelu -> h (split bf16)
// ---------------------------------------------------------------------------
__global__ void h_kernel(const float* __restrict__ ehr_times, const float* __restrict__ itv,
                         const float* __restrict__ w1, const float* __restrict__ b1) {
    __shared__ float3 stf[32];
    int tid = threadIdx.x;
    int g0 = blockIdx.x * 32;
    int b  = g0 / (P_*L_);
    int p  = (g0 / L_) % P_;
    int l0 = g0 % L_;
    if (tid < 32) {
        float t = ehr_times[b*L_ + l0 + tid];
        float s = itv[(b*P_+p)*2 + 0];
        float e = itv[(b*P_+p)*2 + 1];
        float ds = t - s, de = e - t;
        float x  = ds * de;
        float sg = 1.f / (1.f + expf(-x));
        stf[tid] = make_float3(ds, de, sg);
    }
    __syncthreads();
    for (int i = tid; i < 32*DH_; i += 256) {
        int r = i >> 7, j = i & 127;
        float3 tf = stf[r];
        float z = tf.x*w1[j] + tf.y*w1[DH_+j] + tf.z*w1[2*DH_+j] + b1[j];
        float v = 0.5f * z * (1.f + erff(z * 0.70710678118654752f));
        __nv_bfloat16 h, l;
        split1(v, h, l);
        g_hh[(size_t)g0*DH_ + i] = h;
        g_hl[(size_t)g0*DH_ + i] = l;
    }
}

// ---------------------------------------------------------------------------
// Generic bf16 hi/lo 3-product GEMM, ldmatrix fragment loads
// ---------------------------------------------------------------------------
template<int K, bool SPLIT>
__global__ void __launch_bounds__(256)
gemm_kernel(const __nv_bfloat16* __restrict__ Ah, const __nv_bfloat16* __restrict__ Al,
            const __nv_bfloat16* __restrict__ BTh, const __nv_bfloat16* __restrict__ BTl,
            const float* __restrict__ bias,
            float* __restrict__ outF,
            __nv_bfloat16* __restrict__ outH, __nv_bfloat16* __restrict__ outL) {
    __shared__ __nv_bfloat16 sAh[128*40], sAl[128*40], sBh[128*40], sBl[128*40];
    int tid = threadIdx.x, wid = tid >> 5, lane = tid & 31;
    int g = lane >> 2, kq = (lane & 3) * 2;
    int wm = wid & 3, wn = wid >> 2;
    int m0 = blockIdx.x * 128, n0 = blockIdx.y * 128;

    // ldmatrix per-thread address components
    int r8 = lane & 7, q8 = lane >> 3;          // q8: 0..3 -> tile role
    uint32_t sAh_u = smem_u32(sAh), sAl_u = smem_u32(sAl);
    uint32_t sBh_u = smem_u32(sBh), sBl_u = smem_u32(sBl);
    // A tiles: q8&1 -> +8 rows, q8>>1 -> +8 cols
    uint32_t aoff = (uint32_t)((r8 + (q8 & 1) * 8) * 80 + ((q8 >> 1) * 8) * 2);
    // B tiles: q8&1 -> +8 cols, q8>=2 -> lo array
    uint32_t bbase = (q8 >= 2 ? sBl_u : sBh_u)
                   + (uint32_t)((wn*64 + r8) * 80 + ((q8 & 1) * 8) * 2);

    float c[2][8][4];
#pragma unroll
    for (int nt = 0; nt < 8; nt++) {
        float2 bb = *(const float2*)&bias[n0 + wn*64 + nt*8 + kq];
#pragma unroll
        for (int mt = 0; mt < 2; mt++) {
            c[mt][nt][0] = bb.x; c[mt][nt][1] = bb.y;
            c[mt][nt][2] = bb.x; c[mt][nt][3] = bb.y;
        }
    }

    for (int kc = 0; kc < K; kc += 32) {
        for (int idx = tid; idx < 1024; idx += 256) {
            int r = idx >> 3, c4 = (idx & 7) * 4;
            *(uint2*)&sAh[r*40 + c4] = *(const uint2*)&Ah[(size_t)(m0+r)*K + kc + c4];
            *(uint2*)&sAl[r*40 + c4] = *(const uint2*)&Al[(size_t)(m0+r)*K + kc + c4];
            *(uint2*)&sBh[r*40 + c4] = *(const uint2*)&BTh[(size_t)(n0+r)*K + kc + c4];
            *(uint2*)&sBl[r*40 + c4] = *(const uint2*)&BTl[(size_t)(n0+r)*K + kc + c4];
        }
        __syncthreads();
#pragma unroll
        for (int kt = 0; kt < 2; kt++) {
            unsigned ah[2][4], al[2][4];
#pragma unroll
            for (int mt = 0; mt < 2; mt++) {
                uint32_t abyte = aoff + (uint32_t)((wm*32 + mt*16) * 80 + kt*32);
                LDMATRIX_X4(ah[mt][0], ah[mt][1], ah[mt][2], ah[mt][3], sAh_u + abyte);
                LDMATRIX_X4(al[mt][0], al[mt][1], al[mt][2], al[mt][3], sAl_u + abyte);
            }
#pragma unroll
            for (int nt = 0; nt < 8; nt++) {
                unsigned bh[2], bl[2];
                LDMATRIX_X4(bh[0], bh[1], bl[0], bl[1],
                            bbase + (uint32_t)(nt*640 + kt*32));
#pragma unroll
                for (int mt = 0; mt < 2; mt++) {
                    mma16816(c[mt][nt], ah[mt], bh);
                    mma16816(c[mt][nt], al[mt], bh);
                    mma16816(c[mt][nt], ah[mt], bl);
                }
            }
        }
        __syncthreads();
    }

#pragma unroll
    for (int mt = 0; mt < 2; mt++) {
        int r0 = m0 + wm*32 + mt*16 + g;
#pragma unroll
        for (int nt = 0; nt < 8; nt++) {
            int col = n0 + wn*64 + nt*8 + kq;
            if (SPLIT) {
                unsigned h0, l0, h1, l1;
                split2(c[mt][nt][0], c[mt][nt][1], h0, l0);
                split2(c[mt][nt][2], c[mt][nt][3], h1, l1);
                *(unsigned*)&outH[(size_t)r0*D_ + col] = h0;
                *(unsigned*)&outL[(size_t)r0*D_ + col] = l0;
                *(unsigned*)&outH[(size_t)(r0+8)*D_ + col] = h1;
                *(unsigned*)&outL[(size_t)(r0+8)*D_ + col] = l1;
            } else {
                *(float2*)&outF[(size_t)r0*D_ + col] = make_float2(c[mt][nt][0], c[mt][nt][1]);
                *(float2*)&outF[(size_t)(r0+8)*D_ + col] = make_float2(c[mt][nt][2], c[mt][nt][3]);
            }
        }
    }
}

// ---------------------------------------------------------------------------
// Kernel 4: flash attention, online softmax, ldmatrix fragment loads
// ---------------------------------------------------------------------------
#define AKH 0
#define AKL 20480
#define AVH 40960
#define AVL 57856
#define ABI 74752
#define ASM_TOT 75776
#define KP  40
#define VP  264

__global__ void __launch_bounds__(256, 2)
attn_kernel(const float* __restrict__ ehr_times, const float* __restrict__ itv) {
    extern __shared__ char sm[];
    uint32_t sbase = smem_u32(sm);
    int tid = threadIdx.x;
    int wid = tid >> 5, lane = tid & 31;
    int g  = lane >> 2;
    int kq = (lane & 3) * 2;
    int h    = blockIdx.x;
    int half = blockIdx.y;
    int bp   = blockIdx.z;
    int b = bp >> 5;

    {
        const __nv_bfloat16* kh = g_kh + (size_t)(b*L_)*D_ + h*HD_;
        const __nv_bfloat16* kl = g_kl + (size_t)(b*L_)*D_ + h*HD_;
        for (int idx = tid; idx < 2048; idx += 256) {
            int r = idx >> 3, c4 = (idx & 7) * 4;
            *(uint2*)(sm + AKH + r*(KP*2) + c4*2) = *(const uint2*)(kh + r*D_ + c4);
            *(uint2*)(sm + AKL + r*(KP*2) + c4*2) = *(const uint2*)(kl + r*D_ + c4);
        }
    }
    {
        const __nv_bfloat16* vh = g_vth + (size_t)(b*D_ + h*HD_)*L_;
        const __nv_bfloat16* vl = g_vtl + (size_t)(b*D_ + h*HD_)*L_;
        for (int idx = tid; idx < 1024; idx += 256) {
            int hd = idx >> 5, c8 = (idx & 31) * 8;
            *(uint4*)(sm + AVH + hd*(VP*2) + c8*2) = *(const uint4*)(vh + hd*L_ + c8);
            *(uint4*)(sm + AVL + hd*(VP*2) + c8*2) = *(const uint4*)(vl + hd*L_ + c8);
        }
    }
    {
        float s = itv[bp*2 + 0];
        float e = itv[bp*2 + 1];
        float ctr = 0.5f*(s+e);
        float t = ehr_times[b*L_ + tid];
        ((float*)(sm + ABI))[tid] = (t >= s && t <= e) ? -fabsf(t - ctr) : -1e30f;
    }

    unsigned qah[2][4], qal[2][4];
    {
        size_t qrow = (size_t)bp*L_ + half*128 + wid*16;
#pragma unroll
        for (int kt = 0; kt < 2; kt++) {
            size_t base = (qrow + g)*D_ + h*HD_ + kt*16 + kq;
            qah[kt][0] = *(const unsigned*)(g_qh + base);
            qah[kt][1] = *(const unsigned*)(g_qh + base + 8*D_);
            qah[kt][2] = *(const unsigned*)(g_qh + base + 8);
            qah[kt][3] = *(const unsigned*)(g_qh + base + 8*D_ + 8);
            qal[kt][0] = *(const unsigned*)(g_ql + base);
            qal[kt][1] = *(const unsigned*)(g_ql + base + 8*D_);
            qal[kt][2] = *(const unsigned*)(g_ql + base + 8);
            qal[kt][3] = *(const unsigned*)(g_ql + base + 8*D_ + 8);
        }
    }
    __syncthreads();

    // ldmatrix per-thread bases: q8 0/1 -> hi array cols +0/+8, 2/3 -> lo array
    int r8 = lane & 7, q8 = lane >> 3;
    uint32_t kfb = sbase + (q8 >= 2 ? AKL : AKH) + (uint32_t)((q8 & 1) * 16 + r8 * (KP*2));
    uint32_t vfb = sbase + (q8 >= 2 ? AVL : AVH) + (uint32_t)((q8 & 1) * 16 + r8 * (VP*2));

    const float* sb = (const float*)(sm + ABI);
    float m0 = -1e30f, m1 = -1e30f, d0 = 0.f, d1 = 0.f;
    float o[4][4];
#pragma unroll
    for (int nt = 0; nt < 4; nt++) { o[nt][0]=0.f; o[nt][1]=0.f; o[nt][2]=0.f; o[nt][3]=0.f; }

#pragma unroll 1
    for (int ch = 0; ch < 4; ch++) {
        // ---- S chunk = Q K^T for keys [ch*64, ch*64+64) ----
        float c[8][4];
#pragma unroll
        for (int nt = 0; nt < 8; nt++) { c[nt][0]=0.f; c[nt][1]=0.f; c[nt][2]=0.f; c[nt][3]=0.f; }
#pragma unroll
        for (int nt = 0; nt < 8; nt++) {
            uint32_t krow = kfb + (uint32_t)((ch*64 + nt*8) * (KP*2));
#pragma unroll
            for (int kt = 0; kt < 2; kt++) {
                unsigned bh[2], bl[2];
                LDMATRIX_X4(bh[0], bh[1], bl[0], bl[1], krow + (uint32_t)(kt*32));
                mma16816(c[nt], qah[kt], bh);
                mma16816(c[nt], qal[kt], bh);
                mma16816(c[nt], qah[kt], bl);
            }
        }
        // ---- add bias + chunk max ----
        float cm0 = -1e30f, cm1 = -1e30f;
#pragma unroll
        for (int nt = 0; nt < 8; nt++) {
            float2 bb = *(const float2*)&sb[ch*64 + nt*8 + kq];
            c[nt][0] += bb.x; c[nt][1] += bb.y;
            c[nt][2] += bb.x; c[nt][3] += bb.y;
            cm0 = fmaxf(cm0, fmaxf(c[nt][0], c[nt][1]));
            cm1 = fmaxf(cm1, fmaxf(c[nt][2], c[nt][3]));
        }
        cm0 = fmaxf(cm0, __shfl_xor_sync(0xffffffffu, cm0, 1));
        cm0 = fmaxf(cm0, __shfl_xor_sync(0xffffffffu, cm0, 2));
        cm1 = fmaxf(cm1, __shfl_xor_sync(0xffffffffu, cm1, 1));
        cm1 = fmaxf(cm1, __shfl_xor_sync(0xffffffffu, cm1, 2));
        // ---- online rescale ----
        float nm0 = fmaxf(m0, cm0), nm1 = fmaxf(m1, cm1);
        float corr0 = __expf(m0 - nm0), corr1 = __expf(m1 - nm1);
        m0 = nm0; m1 = nm1;
        d0 *= corr0; d1 *= corr1;
#pragma unroll
        for (int nt = 0; nt < 4; nt++) {
            o[nt][0] *= corr0; o[nt][1] *= corr0;
            o[nt][2] *= corr1; o[nt][3] *= corr1;
        }
        // ---- exp + accumulate den (per-lane partial; quad-reduced at end) ----
#pragma unroll
        for (int nt = 0; nt < 8; nt++) {
            c[nt][0] = __expf(c[nt][0] - m0);
            c[nt][1] = __expf(c[nt][1] - m0);
            c[nt][2] = __expf(c[nt][2] - m1);
            c[nt][3] = __expf(c[nt][3] - m1);
            d0 += c[nt][0] + c[nt][1];
            d1 += c[nt][2] + c[nt][3];
        }
        // ---- O += P_chunk * V_chunk ----
#pragma unroll
        for (int kt = 0; kt < 4; kt++) {
            unsigned ah[4], al[4];
            split2(c[2*kt][0],   c[2*kt][1],   ah[0], al[0]);
            split2(c[2*kt][2],   c[2*kt][3],   ah[1], al[1]);
            split2(c[2*kt+1][0], c[2*kt+1][1], ah[2], al[2]);
            split2(c[2*kt+1][2], c[2*kt+1][3], ah[3], al[3]);
            uint32_t vcol = vfb + (uint32_t)((ch*64 + kt*16) * 2);
#pragma unroll
            for (int nt = 0; nt < 4; nt++) {
                unsigned bh[2], bl[2];
                LDMATRIX_X4(bh[0], bh[1], bl[0], bl[1], vcol + (uint32_t)(nt*8*(VP*2)));
                mma16816(o[nt], ah, bh);
                mma16816(o[nt], al, bh);
                mma16816(o[nt], ah, bl);
            }
        }
    }

    // ---- reduce den partials across the quad (m is quad-uniform) ----
    d0 += __shfl_xor_sync(0xffffffffu, d0, 1);
    d0 += __shfl_xor_sync(0xffffffffu, d0, 2);
    d1 += __shfl_xor_sync(0xffffffffu, d1, 1);
    d1 += __shfl_xor_sync(0xffffffffu, d1, 2);

    // ---- epilogue: normalize, split, store ctx ----
    {
        float inv0 = 1.f / d0, inv1 = 1.f / d1;
        size_t orow = (size_t)bp*L_ + half*128 + wid*16;
#pragma unroll
        for (int nt = 0; nt < 4; nt++) {
            unsigned h0, l0, h1, l1;
            split2(o[nt][0]*inv0, o[nt][1]*inv0, h0, l0);
            split2(o[nt][2]*inv1, o[nt][3]*inv1, h1, l1);
            size_t i0 = (orow+g  )*D_ + h*HD_ + nt*8 + kq;
            size_t i1 = (orow+g+8)*D_ + h*HD_ + nt*8 + kq;
            *(unsigned*)&g_ctxh[i0] = h0;
            *(unsigned*)&g_ctxl[i0] = l0;
            *(unsigned*)&g_ctxh[i1] = h1;
            *(unsigned*)&g_ctxl[i1] = l1;
        }
    }
}

// ---------------------------------------------------------------------------
extern "C" void kernel_launch(void* const* d_in, const int* in_sizes, int n_in,
                              void* d_out, int out_size) {
    const float* ehr       = (const float*)d_in[0];
    const float* ehr_times = (const float*)d_in[1];
    const float* itv       = (const float*)d_in[2];
    const float* w1        = (const float*)d_in[3];
    const float* b1        = (const float*)d_in[4];
    const float* w2        = (const float*)d_in[5];
    const float* b2        = (const float*)d_in[6];
    const float* wq        = (const float*)d_in[7];
    const float* bq        = (const float*)d_in[8];
    const float* wk        = (const float*)d_in[9];
    const float* bk        = (const float*)d_in[10];
    const float* wv        = (const float*)d_in[11];
    const float* bv        = (const float*)d_in[12];
    const float* wo        = (const float*)d_in[13];
    const float* bo        = (const float*)d_in[14];
    float* out = (float*)d_out;

    __nv_bfloat16 *p_hh, *p_hl, *p_w2qTh, *p_w2qTl, *p_qh, *p_ql;
    __nv_bfloat16 *p_ctxh, *p_ctxl, *p_woTh, *p_woTl;
    float *p_bq2;
    cudaGetSymbolAddress((void**)&p_hh, g_hh);
    cudaGetSymbolAddress((void**)&p_hl, g_hl);
    cudaGetSymbolAddress((void**)&p_w2qTh, g_w2qTh);
    cudaGetSymbolAddress((void**)&p_w2qTl, g_w2qTl);
    cudaGetSymbolAddress((void**)&p_qh, g_qh);
    cudaGetSymbolAddress((void**)&p_ql, g_ql);
    cudaGetSymbolAddress((void**)&p_ctxh, g_ctxh);
    cudaGetSymbolAddress((void**)&p_ctxl, g_ctxl);
    cudaGetSymbolAddress((void**)&p_woTh, g_woTh);
    cudaGetSymbolAddress((void**)&p_woTl, g_woTl);
    cudaGetSymbolAddress((void**)&p_bq2, g_bq2);

    fuse_w_kernel<<<DH_, D_>>>(w2, wq, b2, bq);
    prep_split_kernel<<<D_, D_>>>(wo);
    kv_kernel<<<B_*L_/8, 256>>>(ehr, wk, bk, wv, bv);
    h_kernel<<<B_*P_*L_/32, 256>>>(ehr_times, itv, w1, b1);

    gemm_kernel<DH_, true><<<dim3(256, 2), 256>>>(
        p_hh, p_hl, p_w2qTh, p_w2qTl, p_bq2, nullptr, p_qh, p_ql);

    cudaFuncSetAttribute(attn_kernel, cudaFuncAttributeMaxDynamicSharedMemorySize, ASM_TOT);
    attn_kernel<<<dim3(H_, 2, B_*P_), 256, ASM_TOT>>>(ehr_times, itv);

    gemm_kernel<D_, false><<<dim3(256, 2), 256>>>(
        p_ctxh, p_ctxl, p_woTh, p_woTl, bo, out, nullptr, nullptr);
}

// round 10
// speedup vs baseline: 1.0748x; 1.0748x over previous
#include <cuda_runtime.h>
#include <cuda_bf16.h>
#include <math.h>
#include <cstdint>

#define B_  4
#define L_  256
#define D_  256
#define P_  32
#define H_  8
#define HD_ 32
#define DH_ 128   // D/2

typedef unsigned long long u64;

// ======================= packed f32x2 helpers ==============================
__device__ __forceinline__ u64 pk2(float lo, float hi) {
    u64 r;
    asm("mov.b64 %0, {%1, %2};" : "=l"(r) : "r"(__float_as_uint(lo)), "r"(__float_as_uint(hi)));
    return r;
}
__device__ __forceinline__ void upk2(u64 v, float& lo, float& hi) {
    unsigned a, b;
    asm("mov.b64 {%0, %1}, %2;" : "=r"(a), "=r"(b) : "l"(v));
    lo = __uint_as_float(a); hi = __uint_as_float(b);
}
__device__ __forceinline__ void fma2(u64& d, u64 a, u64 b) {
    asm("fma.rn.f32x2 %0, %1, %2, %0;" : "+l"(d) : "l"(a), "l"(b));
}

// ======================= mma.sync bf16 + cp.async ==========================
__device__ __forceinline__ void mma16816(float* c, const unsigned* a, const unsigned* b) {
    asm volatile("mma.sync.aligned.m16n8k16.row.col.f32.bf16.bf16.f32 "
        "{%0,%1,%2,%3}, {%4,%5,%6,%7}, {%8,%9}, {%0,%1,%2,%3};"
        : "+f"(c[0]), "+f"(c[1]), "+f"(c[2]), "+f"(c[3])
        : "r"(a[0]), "r"(a[1]), "r"(a[2]), "r"(a[3]), "r"(b[0]), "r"(b[1]));
}
__device__ __forceinline__ uint32_t smem_u32(const void* p) {
    uint32_t a;
    asm("{ .reg .u64 t; cvta.to.shared.u64 t, %1; cvt.u32.u64 %0, t; }" : "=r"(a) : "l"(p));
    return a;
}
__device__ __forceinline__ void cp16(uint32_t dst, const void* src) {
    asm volatile("cp.async.cg.shared.global [%0], [%1], 16;" :: "r"(dst), "l"(src));
}
#define CP_COMMIT() asm volatile("cp.async.commit_group;" ::: "memory")
#define CP_WAIT(n)  asm volatile("cp.async.wait_group %0;" :: "n"(n) : "memory")

__device__ __forceinline__ void split2(float x0, float x1, unsigned& whi, unsigned& wlo) {
    __nv_bfloat16 h0 = __float2bfloat16(x0);
    __nv_bfloat16 h1 = __float2bfloat16(x1);
    __nv_bfloat16 l0 = __float2bfloat16(x0 - __bfloat162float(h0));
    __nv_bfloat16 l1 = __float2bfloat16(x1 - __bfloat162float(h1));
    whi = (unsigned)*(unsigned short*)&h0 | ((unsigned)*(unsigned short*)&h1 << 16);
    wlo = (unsigned)*(unsigned short*)&l0 | ((unsigned)*(unsigned short*)&l1 << 16);
}
__device__ __forceinline__ void split1(float x, __nv_bfloat16& h, __nv_bfloat16& l) {
    h = __float2bfloat16(x);
    l = __float2bfloat16(x - __bfloat162float(h));
}

// ======================= scratch =========================================
__device__ __nv_bfloat16 g_kh[B_*L_*D_];
__device__ __nv_bfloat16 g_kl[B_*L_*D_];
__device__ __nv_bfloat16 g_vth[B_*D_*L_];       // [(b*D + c)][l]
__device__ __nv_bfloat16 g_vtl[B_*D_*L_];
__device__ __nv_bfloat16 g_qh[B_*P_*L_*D_];
__device__ __nv_bfloat16 g_ql[B_*P_*L_*D_];
__device__ __nv_bfloat16 g_ctxh[B_*P_*L_*D_];
__device__ __nv_bfloat16 g_ctxl[B_*P_*L_*D_];
__device__ __nv_bfloat16 g_hh[B_*P_*L_*DH_];
__device__ __nv_bfloat16 g_hl[B_*P_*L_*DH_];
__device__ __nv_bfloat16 g_woTh[D_*D_];         // [n][k]
__device__ __nv_bfloat16 g_woTl[D_*D_];
__device__ __nv_bfloat16 g_w2qTh[D_*DH_];       // [n][k], scale folded
__device__ __nv_bfloat16 g_w2qTl[D_*DH_];
__device__ float g_W2q[DH_*D_];
__device__ float g_bq2[D_];                     // scale folded

// ---------------------------------------------------------------------------
// Kernel 1: W2q = w2 @ wq, bq2 = scale*(b2 @ wq + bq)
// ---------------------------------------------------------------------------
__global__ void fuse_w_kernel(const float* __restrict__ w2, const float* __restrict__ wq,
                              const float* __restrict__ b2, const float* __restrict__ bq) {
    int j = blockIdx.x, c = threadIdx.x;
    float acc = 0.f;
    for (int k = 0; k < D_; k++) acc = fmaf(w2[j*D_+k], wq[k*D_+c], acc);
    g_W2q[j*D_+c] = acc;
    if (j == 0) {
        float a = 0.f;
        for (int k = 0; k < D_; k++) a = fmaf(b2[k], wq[k*D_+c], a);
        g_bq2[c] = 0.17677669529663687f * (a + bq[c]);
    }
}

// ---------------------------------------------------------------------------
// Kernel 1b: transpose+split wo and scale*W2q
// ---------------------------------------------------------------------------
__global__ void prep_split_kernel(const float* __restrict__ wo) {
    int n = blockIdx.x, k = threadIdx.x;
    __nv_bfloat16 h, l;
    split1(wo[k*D_ + n], h, l);
    g_woTh[n*D_ + k] = h;
    g_woTl[n*D_ + k] = l;
    if (k < DH_) {
        split1(0.17677669529663687f * g_W2q[k*D_ + n], h, l);
        g_w2qTh[n*DH_ + k] = h;
        g_w2qTl[n*DH_ + k] = l;
    }
}

// ---------------------------------------------------------------------------
// Kernel 2: k/v projections, packed f32x2 accumulate (bit-identical order)
// ---------------------------------------------------------------------------
__global__ void kv_kernel(const float* __restrict__ ehr,
                          const float* __restrict__ wk, const float* __restrict__ bk,
                          const float* __restrict__ wv, const float* __restrict__ bv) {
    __shared__ float sx[8*D_];
    int row0 = blockIdx.x * 8;
    int tid = threadIdx.x;
    for (int i = tid; i < 8*D_; i += 256) sx[i] = ehr[row0*D_ + i];
    __syncthreads();
    int c = tid;
    u64 acc[8];                           // (k, v) packed per row
    {
        u64 b0 = pk2(bk[c], bv[c]);
#pragma unroll
        for (int r = 0; r < 8; r++) acc[r] = b0;
    }
    for (int d = 0; d < D_; d++) {
        u64 w = pk2(wk[d*D_+c], wv[d*D_+c]);
#pragma unroll
        for (int r = 0; r < 8; r++) {
            float x = sx[r*D_+d];
            fma2(acc[r], pk2(x, x), w);
        }
    }
    float ak[8], av[8];
#pragma unroll
    for (int r = 0; r < 8; r++) upk2(acc[r], ak[r], av[r]);
#pragma unroll
    for (int r = 0; r < 8; r++) {
        __nv_bfloat16 h, l;
        split1(ak[r], h, l);
        g_kh[(row0+r)*D_+c] = h;
        g_kl[(row0+r)*D_+c] = l;
    }
    {
        int b  = row0 / L_;
        int l0 = row0 % L_;
        __nv_bfloat16 vh8[8], vl8[8];
#pragma unroll
        for (int r = 0; r < 8; r++) split1(av[r], vh8[r], vl8[r]);
        *(uint4*)&g_vth[(b*D_ + c)*L_ + l0] = *(uint4*)vh8;
        *(uint4*)&g_vtl[(b*D_ + c)*L_ + l0] = *(uint4*)vl8;
    }
}

// ---------------------------------------------------------------------------
// Kernel 3: time features -> MLP -> gelu -> h (split bf16)
// ---------------------------------------------------------------------------
__global__ void h_kernel(const float* __restrict__ ehr_times, const float* __restrict__ itv,
                         const float* __restrict__ w1, const float* __restrict__ b1) {
    __shared__ float3 stf[32];
    int tid = threadIdx.x;
    int g0 = blockIdx.x * 32;
    int b  = g0 / (P_*L_);
    int p  = (g0 / L_) % P_;
    int l0 = g0 % L_;
    if (tid < 32) {
        float t = ehr_times[b*L_ + l0 + tid];
        float s = itv[(b*P_+p)*2 + 0];
        float e = itv[(b*P_+p)*2 + 1];
        float ds = t - s, de = e - t;
        float x  = ds * de;
        float sg = 1.f / (1.f + expf(-x));
        stf[tid] = make_float3(ds, de, sg);
    }
    __syncthreads();
    for (int i = tid; i < 32*DH_; i += 256) {
        int r = i >> 7, j = i & 127;
        float3 tf = stf[r];
        float z = tf.x*w1[j] + tf.y*w1[DH_+j] + tf.z*w1[2*DH_+j] + b1[j];
        float v = 0.5f * z * (1.f + erff(z * 0.70710678118654752f));
        __nv_bfloat16 h, l;
        split1(v, h, l);
        g_hh[(size_t)g0*DH_ + i] = h;
        g_hl[(size_t)g0*DH_ + i] = l;
    }
}

// ---------------------------------------------------------------------------
// Generic bf16 hi/lo 3-product GEMM, 2-stage cp.async pipeline.
// Dynamic smem: 2 stages x (4 arrays x 5120 bf16) = 81920 B.
// Per-stage layout: [sAh | sAl | sBh | sBl], pitch 40 bf16 per row.
// ---------------------------------------------------------------------------
#define GSTAGE 20480   // bf16 elems per stage

template<int K, bool SPLIT>
__global__ void __launch_bounds__(256)
gemm_kernel(const __nv_bfloat16* __restrict__ Ah, const __nv_bfloat16* __restrict__ Al,
            const __nv_bfloat16* __restrict__ BTh, const __nv_bfloat16* __restrict__ BTl,
            const float* __restrict__ bias,
            float* __restrict__ outF,
            __nv_bfloat16* __restrict__ outH, __nv_bfloat16* __restrict__ outL) {
    extern __shared__ __nv_bfloat16 gsm[];
    int tid = threadIdx.x, wid = tid >> 5, lane = tid & 31;
    int g = lane >> 2, kq = (lane & 3) * 2;
    int wm = wid & 3, wn = wid >> 2;
    int m0 = blockIdx.x * 128, n0 = blockIdx.y * 128;
    uint32_t gsm_u = smem_u32(gsm);

    // async load of one 32-K chunk into a stage (512 x 16B per array)
    auto load_chunk = [&](int st, int kc) {
        uint32_t sb = gsm_u + (uint32_t)st * (GSTAGE * 2);
        for (int idx = tid; idx < 512; idx += 256) {
            int r = idx >> 2, c8 = (idx & 3) * 8;
            uint32_t so = (uint32_t)(r*40 + c8) * 2;
            cp16(sb + so,             &Ah [(size_t)(m0+r)*K + kc + c8]);
            cp16(sb + 10240 + so,     &Al [(size_t)(m0+r)*K + kc + c8]);
            cp16(sb + 20480 + so,     &BTh[(size_t)(n0+r)*K + kc + c8]);
            cp16(sb + 30720 + so,     &BTl[(size_t)(n0+r)*K + kc + c8]);
        }
    };

    float c[2][8][4];
#pragma unroll
    for (int nt = 0; nt < 8; nt++) {
        float2 bb = *(const float2*)&bias[n0 + wn*64 + nt*8 + kq];
#pragma unroll
        for (int mt = 0; mt < 2; mt++) {
            c[mt][nt][0] = bb.x; c[mt][nt][1] = bb.y;
            c[mt][nt][2] = bb.x; c[mt][nt][3] = bb.y;
        }
    }

    constexpr int NC = K / 32;
    load_chunk(0, 0);
    CP_COMMIT();

#pragma unroll 1
    for (int ci = 0; ci < NC; ci++) {
        if (ci + 1 < NC) {
            load_chunk((ci + 1) & 1, (ci + 1) * 32);
            CP_COMMIT();
            CP_WAIT(1);
        } else {
            CP_WAIT(0);
        }
        __syncthreads();

        const __nv_bfloat16* sAh = gsm + (ci & 1) * GSTAGE;
        const __nv_bfloat16* sAl = sAh + 5120;
        const __nv_bfloat16* sBh = sAh + 10240;
        const __nv_bfloat16* sBl = sAh + 15360;
#pragma unroll
        for (int kt = 0; kt < 2; kt++) {
            unsigned ah[2][4], al[2][4];
#pragma unroll
            for (int mt = 0; mt < 2; mt++) {
                int rb = wm*32 + mt*16;
                ah[mt][0] = *(const unsigned*)&sAh[(rb+g  )*40 + kt*16 + kq];
                ah[mt][1] = *(const unsigned*)&sAh[(rb+g+8)*40 + kt*16 + kq];
                ah[mt][2] = *(const unsigned*)&sAh[(rb+g  )*40 + kt*16 + kq + 8];
                ah[mt][3] = *(const unsigned*)&sAh[(rb+g+8)*40 + kt*16 + kq + 8];
                al[mt][0] = *(const unsigned*)&sAl[(rb+g  )*40 + kt*16 + kq];
                al[mt][1] = *(const unsigned*)&sAl[(rb+g+8)*40 + kt*16 + kq];
                al[mt][2] = *(const unsigned*)&sAl[(rb+g  )*40 + kt*16 + kq + 8];
                al[mt][3] = *(const unsigned*)&sAl[(rb+g+8)*40 + kt*16 + kq + 8];
            }
#pragma unroll
            for (int nt = 0; nt < 8; nt++) {
                int rn = wn*64 + nt*8 + g;
                unsigned bh[2], bl[2];
                bh[0] = *(const unsigned*)&sBh[rn*40 + kt*16 + kq];
                bh[1] = *(const unsigned*)&sBh[rn*40 + kt*16 + kq + 8];
                bl[0] = *(const unsigned*)&sBl[rn*40 + kt*16 + kq];
                bl[1] = *(const unsigned*)&sBl[rn*40 + kt*16 + kq + 8];
#pragma unroll
                for (int mt = 0; mt < 2; mt++) {
                    mma16816(c[mt][nt], ah[mt], bh);
                    mma16816(c[mt][nt], al[mt], bh);
                    mma16816(c[mt][nt], ah[mt], bl);
                }
            }
        }
        __syncthreads();
    }

#pragma unroll
    for (int mt = 0; mt < 2; mt++) {
        int r0 = m0 + wm*32 + mt*16 + g;
#pragma unroll
        for (int nt = 0; nt < 8; nt++) {
            int col = n0 + wn*64 + nt*8 + kq;
            if (SPLIT) {
                unsigned h0, l0, h1, l1;
                split2(c[mt][nt][0], c[mt][nt][1], h0, l0);
                split2(c[mt][nt][2], c[mt][nt][3], h1, l1);
                *(unsigned*)&outH[(size_t)r0*D_ + col] = h0;
                *(unsigned*)&outL[(size_t)r0*D_ + col] = l0;
                *(unsigned*)&outH[(size_t)(r0+8)*D_ + col] = h1;
                *(unsigned*)&outL[(size_t)(r0+8)*D_ + col] = l1;
            } else {
                *(float2*)&outF[(size_t)r0*D_ + col] = make_float2(c[mt][nt][0], c[mt][nt][1]);
                *(float2*)&outF[(size_t)(r0+8)*D_ + col] = make_float2(c[mt][nt][2], c[mt][nt][3]);
            }
        }
    }
}
#define GSM_TOT (2 * GSTAGE * 2)   // 81920 bytes

// ---------------------------------------------------------------------------
// Kernel 4: flash attention, online softmax (R8 version, scalar LDS)
// ---------------------------------------------------------------------------
#define AKH 0
#define AKL 20480
#define AVH 40960
#define AVL 57856
#define ABI 74752
#define ASM_TOT 75776
#define KP  40
#define VP  264

__global__ void __launch_bounds__(256, 2)
attn_kernel(const float* __restrict__ ehr_times, const float* __restrict__ itv) {
    extern __shared__ char sm[];
    int tid = threadIdx.x;
    int wid = tid >> 5, lane = tid & 31;
    int g  = lane >> 2;
    int kq = (lane & 3) * 2;
    int h    = blockIdx.x;
    int half = blockIdx.y;
    int bp   = blockIdx.z;
    int b = bp >> 5;

    {
        const __nv_bfloat16* kh = g_kh + (size_t)(b*L_)*D_ + h*HD_;
        const __nv_bfloat16* kl = g_kl + (size_t)(b*L_)*D_ + h*HD_;
        for (int idx = tid; idx < 2048; idx += 256) {
            int r = idx >> 3, c4 = (idx & 7) * 4;
            *(uint2*)(sm + AKH + r*(KP*2) + c4*2) = *(const uint2*)(kh + r*D_ + c4);
            *(uint2*)(sm + AKL + r*(KP*2) + c4*2) = *(const uint2*)(kl + r*D_ + c4);
        }
    }
    {
        const __nv_bfloat16* vh = g_vth + (size_t)(b*D_ + h*HD_)*L_;
        const __nv_bfloat16* vl = g_vtl + (size_t)(b*D_ + h*HD_)*L_;
        for (int idx = tid; idx < 1024; idx += 256) {
            int hd = idx >> 5, c8 = (idx & 31) * 8;
            *(uint4*)(sm + AVH + hd*(VP*2) + c8*2) = *(const uint4*)(vh + hd*L_ + c8);
            *(uint4*)(sm + AVL + hd*(VP*2) + c8*2) = *(const uint4*)(vl + hd*L_ + c8);
        }
    }
    {
        float s = itv[bp*2 + 0];
        float e = itv[bp*2 + 1];
        float ctr = 0.5f*(s+e);
        float t = ehr_times[b*L_ + tid];
        ((float*)(sm + ABI))[tid] = (t >= s && t <= e) ? -fabsf(t - ctr) : -1e30f;
    }

    unsigned qah[2][4], qal[2][4];
    {
        size_t qrow = (size_t)bp*L_ + half*128 + wid*16;
#pragma unroll
        for (int kt = 0; kt < 2; kt++) {
            size_t base = (qrow + g)*D_ + h*HD_ + kt*16 + kq;
            qah[kt][0] = *(const unsigned*)(g_qh + base);
            qah[kt][1] = *(const unsigned*)(g_qh + base + 8*D_);
            qah[kt][2] = *(const unsigned*)(g_qh + base + 8);
            qah[kt][3] = *(const unsigned*)(g_qh + base + 8*D_ + 8);
            qal[kt][0] = *(const unsigned*)(g_ql + base);
            qal[kt][1] = *(const unsigned*)(g_ql + base + 8*D_);
            qal[kt][2] = *(const unsigned*)(g_ql + base + 8);
            qal[kt][3] = *(const unsigned*)(g_ql + base + 8*D_ + 8);
        }
    }
    __syncthreads();

    const float* sb = (const float*)(sm + ABI);
    float m0 = -1e30f, m1 = -1e30f, d0 = 0.f, d1 = 0.f;
    float o[4][4];
#pragma unroll
    for (int nt = 0; nt < 4; nt++) { o[nt][0]=0.f; o[nt][1]=0.f; o[nt][2]=0.f; o[nt][3]=0.f; }

#pragma unroll 1
    for (int ch = 0; ch < 4; ch++) {
        float c[8][4];
#pragma unroll
        for (int nt = 0; nt < 8; nt++) { c[nt][0]=0.f; c[nt][1]=0.f; c[nt][2]=0.f; c[nt][3]=0.f; }
#pragma unroll
        for (int nt = 0; nt < 8; nt++) {
            const char* kb = sm + (ch*64 + nt*8 + g)*(KP*2);
#pragma unroll
            for (int kt = 0; kt < 2; kt++) {
                unsigned bh[2], bl[2];
                bh[0] = *(const unsigned*)(kb + AKH + (kt*16 + kq)*2);
                bh[1] = *(const unsigned*)(kb + AKH + (kt*16 + kq)*2 + 16);
                bl[0] = *(const unsigned*)(kb + AKL + (kt*16 + kq)*2);
                bl[1] = *(const unsigned*)(kb + AKL + (kt*16 + kq)*2 + 16);
                mma16816(c[nt], qah[kt], bh);
                mma16816(c[nt], qal[kt], bh);
                mma16816(c[nt], qah[kt], bl);
            }
        }
        float cm0 = -1e30f, cm1 = -1e30f;
#pragma unroll
        for (int nt = 0; nt < 8; nt++) {
            float2 bb = *(const float2*)&sb[ch*64 + nt*8 + kq];
            c[nt][0] += bb.x; c[nt][1] += bb.y;
            c[nt][2] += bb.x; c[nt][3] += bb.y;
            cm0 = fmaxf(cm0, fmaxf(c[nt][0], c[nt][1]));
            cm1 = fmaxf(cm1, fmaxf(c[nt][2], c[nt][3]));
        }
        cm0 = fmaxf(cm0, __shfl_xor_sync(0xffffffffu, cm0, 1));
        cm0 = fmaxf(cm0, __shfl_xor_sync(0xffffffffu, cm0, 2));
        cm1 = fmaxf(cm1, __shfl_xor_sync(0xffffffffu, cm1, 1));
        cm1 = fmaxf(cm1, __shfl_xor_sync(0xffffffffu, cm1, 2));
        float nm0 = fmaxf(m0, cm0), nm1 = fmaxf(m1, cm1);
        float corr0 = __expf(m0 - nm0), corr1 = __expf(m1 - nm1);
        m0 = nm0; m1 = nm1;
        d0 *= corr0; d1 *= corr1;
#pragma unroll
        for (int nt = 0; nt < 4; nt++) {
            o[nt][0] *= corr0; o[nt][1] *= corr0;
            o[nt][2] *= corr1; o[nt][3] *= corr1;
        }
#pragma unroll
        for (int nt = 0; nt < 8; nt++) {
            c[nt][0] = __expf(c[nt][0] - m0);
            c[nt][1] = __expf(c[nt][1] - m0);
            c[nt][2] = __expf(c[nt][2] - m1);
            c[nt][3] = __expf(c[nt][3] - m1);
            d0 += c[nt][0] + c[nt][1];
            d1 += c[nt][2] + c[nt][3];
        }
#pragma unroll
        for (int kt = 0; kt < 4; kt++) {
            unsigned ah[4], al[4];
            split2(c[2*kt][0],   c[2*kt][1],   ah[0], al[0]);
            split2(c[2*kt][2],   c[2*kt][3],   ah[1], al[1]);
            split2(c[2*kt+1][0], c[2*kt+1][1], ah[2], al[2]);
            split2(c[2*kt+1][2], c[2*kt+1][3], ah[3], al[3]);
#pragma unroll
            for (int nt = 0; nt < 4; nt++) {
                const char* vb = sm + (nt*8 + g)*(VP*2) + (ch*64 + kt*16 + kq)*2;
                unsigned bh[2], bl[2];
                bh[0] = *(const unsigned*)(vb + AVH);
                bh[1] = *(const unsigned*)(vb + AVH + 16);
                bl[0] = *(const unsigned*)(vb + AVL);
                bl[1] = *(const unsigned*)(vb + AVL + 16);
                mma16816(o[nt], ah, bh);
                mma16816(o[nt], al, bh);
                mma16816(o[nt], ah, bl);
            }
        }
    }

    d0 += __shfl_xor_sync(0xffffffffu, d0, 1);
    d0 += __shfl_xor_sync(0xffffffffu, d0, 2);
    d1 += __shfl_xor_sync(0xffffffffu, d1, 1);
    d1 += __shfl_xor_sync(0xffffffffu, d1, 2);

    {
        float inv0 = 1.f / d0, inv1 = 1.f / d1;
        size_t orow = (size_t)bp*L_ + half*128 + wid*16;
#pragma unroll
        for (int nt = 0; nt < 4; nt++) {
            unsigned h0, l0, h1, l1;
            split2(o[nt][0]*inv0, o[nt][1]*inv0, h0, l0);
            split2(o[nt][2]*inv1, o[nt][3]*inv1, h1, l1);
            size_t i0 = (orow+g  )*D_ + h*HD_ + nt*8 + kq;
            size_t i1 = (orow+g+8)*D_ + h*HD_ + nt*8 + kq;
            *(unsigned*)&g_ctxh[i0] = h0;
            *(unsigned*)&g_ctxl[i0] = l0;
            *(unsigned*)&g_ctxh[i1] = h1;
            *(unsigned*)&g_ctxl[i1] = l1;
        }
    }
}

// ---------------------------------------------------------------------------
extern "C" void kernel_launch(void* const* d_in, const int* in_sizes, int n_in,
                              void* d_out, int out_size) {
    const float* ehr       = (const float*)d_in[0];
    const float* ehr_times = (const float*)d_in[1];
    const float* itv       = (const float*)d_in[2];
    const float* w1        = (const float*)d_in[3];
    const float* b1        = (const float*)d_in[4];
    const float* w2        = (const float*)d_in[5];
    const float* b2        = (const float*)d_in[6];
    const float* wq        = (const float*)d_in[7];
    const float* bq        = (const float*)d_in[8];
    const float* wk        = (const float*)d_in[9];
    const float* bk        = (const float*)d_in[10];
    const float* wv        = (const float*)d_in[11];
    const float* bv        = (const float*)d_in[12];
    const float* wo        = (const float*)d_in[13];
    const float* bo        = (const float*)d_in[14];
    float* out = (float*)d_out;

    __nv_bfloat16 *p_hh, *p_hl, *p_w2qTh, *p_w2qTl, *p_qh, *p_ql;
    __nv_bfloat16 *p_ctxh, *p_ctxl, *p_woTh, *p_woTl;
    float *p_bq2;
    cudaGetSymbolAddress((void**)&p_hh, g_hh);
    cudaGetSymbolAddress((void**)&p_hl, g_hl);
    cudaGetSymbolAddress((void**)&p_w2qTh, g_w2qTh);
    cudaGetSymbolAddress((void**)&p_w2qTl, g_w2qTl);
    cudaGetSymbolAddress((void**)&p_qh, g_qh);
    cudaGetSymbolAddress((void**)&p_ql, g_ql);
    cudaGetSymbolAddress((void**)&p_ctxh, g_ctxh);
    cudaGetSymbolAddress((void**)&p_ctxl, g_ctxl);
    cudaGetSymbolAddress((void**)&p_woTh, g_woTh);
    cudaGetSymbolAddress((void**)&p_woTl, g_woTl);
    cudaGetSymbolAddress((void**)&p_bq2, g_bq2);

    fuse_w_kernel<<<DH_, D_>>>(w2, wq, b2, bq);
    prep_split_kernel<<<D_, D_>>>(wo);
    kv_kernel<<<B_*L_/8, 256>>>(ehr, wk, bk, wv, bv);
    h_kernel<<<B_*P_*L_/32, 256>>>(ehr_times, itv, w1, b1);

    cudaFuncSetAttribute(gemm_kernel<DH_, true>,
                         cudaFuncAttributeMaxDynamicSharedMemorySize, GSM_TOT);
    gemm_kernel<DH_, true><<<dim3(256, 2), 256, GSM_TOT>>>(
        p_hh, p_hl, p_w2qTh, p_w2qTl, p_bq2, nullptr, p_qh, p_ql);

    cudaFuncSetAttribute(attn_kernel, cudaFuncAttributeMaxDynamicSharedMemorySize, ASM_TOT);
    attn_kernel<<<dim3(H_, 2, B_*P_), 256, ASM_TOT>>>(ehr_times, itv);

    cudaFuncSetAttribute(gemm_kernel<D_, false>,
                         cudaFuncAttributeMaxDynamicSharedMemorySize, GSM_TOT);
    gemm_kernel<D_, false><<<dim3(256, 2), 256, GSM_TOT>>>(
        p_ctxh, p_ctxl, p_woTh, p_woTl, bo, out, nullptr, nullptr);
}

// round 11
// speedup vs baseline: 1.2372x; 1.1511x over previous
#include <cuda_runtime.h>
#include <cuda_bf16.h>
#include <math.h>
#include <cstdint>

#define B_  4
#define L_  256
#define D_  256
#define P_  32
#define H_  8
#define HD_ 32
#define DH_ 128   // D/2

// ======================= mma.sync bf16 =====================================
__device__ __forceinline__ void mma16816(float* c, const unsigned* a, const unsigned* b) {
    asm volatile("mma.sync.aligned.m16n8k16.row.col.f32.bf16.bf16.f32 "
        "{%0,%1,%2,%3}, {%4,%5,%6,%7}, {%8,%9}, {%0,%1,%2,%3};"
        : "+f"(c[0]), "+f"(c[1]), "+f"(c[2]), "+f"(c[3])
        : "r"(a[0]), "r"(a[1]), "r"(a[2]), "r"(a[3]), "r"(b[0]), "r"(b[1]));
}
__device__ __forceinline__ void split2(float x0, float x1, unsigned& whi, unsigned& wlo) {
    __nv_bfloat16 h0 = __float2bfloat16(x0);
    __nv_bfloat16 h1 = __float2bfloat16(x1);
    __nv_bfloat16 l0 = __float2bfloat16(x0 - __bfloat162float(h0));
    __nv_bfloat16 l1 = __float2bfloat16(x1 - __bfloat162float(h1));
    whi = (unsigned)*(unsigned short*)&h0 | ((unsigned)*(unsigned short*)&h1 << 16);
    wlo = (unsigned)*(unsigned short*)&l0 | ((unsigned)*(unsigned short*)&l1 << 16);
}
__device__ __forceinline__ unsigned pack_bf16x2(float x0, float x1) {
    __nv_bfloat162 t = __floats2bfloat162_rn(x0, x1);
    return *reinterpret_cast<unsigned*>(&t);
}
__device__ __forceinline__ void split1(float x, __nv_bfloat16& h, __nv_bfloat16& l) {
    h = __float2bfloat16(x);
    l = __float2bfloat16(x - __bfloat162float(h));
}

// ======================= scratch =========================================
__device__ __nv_bfloat16 g_kh[B_*L_*D_];        // K single bf16
__device__ __nv_bfloat16 g_vth[B_*D_*L_];       // V^T hi  [(b*D + c)][l]
__device__ __nv_bfloat16 g_vtl[B_*D_*L_];       // V^T lo
__device__ __nv_bfloat16 g_qh[B_*P_*L_*D_];     // q single bf16
__device__ __nv_bfloat16 g_ctxh[B_*P_*L_*D_];
__device__ __nv_bfloat16 g_ctxl[B_*P_*L_*D_];
__device__ __nv_bfloat16 g_hh[B_*P_*L_*DH_];
__device__ __nv_bfloat16 g_hl[B_*P_*L_*DH_];
__device__ __nv_bfloat16 g_woTh[D_*D_];         // [n][k]
__device__ __nv_bfloat16 g_woTl[D_*D_];
__device__ __nv_bfloat16 g_w2qTh[D_*DH_];       // [n][k], scale folded
__device__ __nv_bfloat16 g_w2qTl[D_*DH_];
__device__ float g_W2q[DH_*D_];
__device__ float g_bq2[D_];                     // scale folded

// ---------------------------------------------------------------------------
// Kernel 1: W2q = w2 @ wq, bq2 = scale*(b2 @ wq + bq)
// ---------------------------------------------------------------------------
__global__ void fuse_w_kernel(const float* __restrict__ w2, const float* __restrict__ wq,
                              const float* __restrict__ b2, const float* __restrict__ bq) {
    int j = blockIdx.x, c = threadIdx.x;
    float acc = 0.f;
    for (int k = 0; k < D_; k++) acc = fmaf(w2[j*D_+k], wq[k*D_+c], acc);
    g_W2q[j*D_+c] = acc;
    if (j == 0) {
        float a = 0.f;
        for (int k = 0; k < D_; k++) a = fmaf(b2[k], wq[k*D_+c], a);
        g_bq2[c] = 0.17677669529663687f * (a + bq[c]);
    }
}

// ---------------------------------------------------------------------------
// Kernel 1b: transpose+split wo and scale*W2q
// ---------------------------------------------------------------------------
__global__ void prep_split_kernel(const float* __restrict__ wo) {
    int n = blockIdx.x, k = threadIdx.x;
    __nv_bfloat16 h, l;
    split1(wo[k*D_ + n], h, l);
    g_woTh[n*D_ + k] = h;
    g_woTl[n*D_ + k] = l;
    if (k < DH_) {
        split1(0.17677669529663687f * g_W2q[k*D_ + n], h, l);
        g_w2qTh[n*DH_ + k] = h;
        g_w2qTl[n*DH_ + k] = l;
    }
}

// ---------------------------------------------------------------------------
// Kernel 2: k/v projections (R8 scalar form). K -> single bf16; V -> hi/lo ^T.
// ---------------------------------------------------------------------------
__global__ void kv_kernel(const float* __restrict__ ehr,
                          const float* __restrict__ wk, const float* __restrict__ bk,
                          const float* __restrict__ wv, const float* __restrict__ bv) {
    __shared__ float sx[8*D_];
    int row0 = blockIdx.x * 8;
    int tid = threadIdx.x;
    for (int i = tid; i < 8*D_; i += 256) sx[i] = ehr[row0*D_ + i];
    __syncthreads();
    int c = tid;
    float ak[8], av[8];
    float bkc = bk[c], bvc = bv[c];
#pragma unroll
    for (int r = 0; r < 8; r++) { ak[r] = bkc; av[r] = bvc; }
    for (int d = 0; d < D_; d++) {
        float wkd = wk[d*D_+c];
        float wvd = wv[d*D_+c];
#pragma unroll
        for (int r = 0; r < 8; r++) {
            float x = sx[r*D_+d];
            ak[r] = fmaf(x, wkd, ak[r]);
            av[r] = fmaf(x, wvd, av[r]);
        }
    }
#pragma unroll
    for (int r = 0; r < 8; r++)
        g_kh[(row0+r)*D_+c] = __float2bfloat16(ak[r]);
    {
        int b  = row0 / L_;
        int l0 = row0 % L_;
        __nv_bfloat16 vh8[8], vl8[8];
#pragma unroll
        for (int r = 0; r < 8; r++) split1(av[r], vh8[r], vl8[r]);
        *(uint4*)&g_vth[(b*D_ + c)*L_ + l0] = *(uint4*)vh8;
        *(uint4*)&g_vtl[(b*D_ + c)*L_ + l0] = *(uint4*)vl8;
    }
}

// ---------------------------------------------------------------------------
// Kernel 3: time features -> MLP -> gelu -> h (split bf16)
// ---------------------------------------------------------------------------
__global__ void h_kernel(const float* __restrict__ ehr_times, const float* __restrict__ itv,
                         const float* __restrict__ w1, const float* __restrict__ b1) {
    __shared__ float3 stf[32];
    int tid = threadIdx.x;
    int g0 = blockIdx.x * 32;
    int b  = g0 / (P_*L_);
    int p  = (g0 / L_) % P_;
    int l0 = g0 % L_;
    if (tid < 32) {
        float t = ehr_times[b*L_ + l0 + tid];
        float s = itv[(b*P_+p)*2 + 0];
        float e = itv[(b*P_+p)*2 + 1];
        float ds = t - s, de = e - t;
        float x  = ds * de;
        float sg = 1.f / (1.f + expf(-x));
        stf[tid] = make_float3(ds, de, sg);
    }
    __syncthreads();
    for (int i = tid; i < 32*DH_; i += 256) {
        int r = i >> 7, j = i & 127;
        float3 tf = stf[r];
        float z = tf.x*w1[j] + tf.y*w1[DH_+j] + tf.z*w1[2*DH_+j] + b1[j];
        float v = 0.5f * z * (1.f + erff(z * 0.70710678118654752f));
        __nv_bfloat16 h, l;
        split1(v, h, l);
        g_hh[(size_t)g0*DH_ + i] = h;
        g_hl[(size_t)g0*DH_ + i] = l;
    }
}

// ---------------------------------------------------------------------------
// Generic bf16 hi/lo 3-product GEMM (R8 static-smem form).
// SPLIT=true: epilogue writes SINGLE rounded bf16 to outH (for q).
// ---------------------------------------------------------------------------
template<int K, bool SPLIT>
__global__ void __launch_bounds__(256)
gemm_kernel(const __nv_bfloat16* __restrict__ Ah, const __nv_bfloat16* __restrict__ Al,
            const __nv_bfloat16* __restrict__ BTh, const __nv_bfloat16* __restrict__ BTl,
            const float* __restrict__ bias,
            float* __restrict__ outF,
            __nv_bfloat16* __restrict__ outH) {
    __shared__ __nv_bfloat16 sAh[128*40], sAl[128*40], sBh[128*40], sBl[128*40];
    int tid = threadIdx.x, wid = tid >> 5, lane = tid & 31;
    int g = lane >> 2, kq = (lane & 3) * 2;
    int wm = wid & 3, wn = wid >> 2;
    int m0 = blockIdx.x * 128, n0 = blockIdx.y * 128;

    float c[2][8][4];
#pragma unroll
    for (int nt = 0; nt < 8; nt++) {
        float2 bb = *(const float2*)&bias[n0 + wn*64 + nt*8 + kq];
#pragma unroll
        for (int mt = 0; mt < 2; mt++) {
            c[mt][nt][0] = bb.x; c[mt][nt][1] = bb.y;
            c[mt][nt][2] = bb.x; c[mt][nt][3] = bb.y;
        }
    }

    for (int kc = 0; kc < K; kc += 32) {
        for (int idx = tid; idx < 1024; idx += 256) {
            int r = idx >> 3, c4 = (idx & 7) * 4;
            *(uint2*)&sAh[r*40 + c4] = *(const uint2*)&Ah[(size_t)(m0+r)*K + kc + c4];
            *(uint2*)&sAl[r*40 + c4] = *(const uint2*)&Al[(size_t)(m0+r)*K + kc + c4];
            *(uint2*)&sBh[r*40 + c4] = *(const uint2*)&BTh[(size_t)(n0+r)*K + kc + c4];
            *(uint2*)&sBl[r*40 + c4] = *(const uint2*)&BTl[(size_t)(n0+r)*K + kc + c4];
        }
        __syncthreads();
#pragma unroll
        for (int kt = 0; kt < 2; kt++) {
            unsigned ah[2][4], al[2][4];
#pragma unroll
            for (int mt = 0; mt < 2; mt++) {
                int rb = wm*32 + mt*16;
                ah[mt][0] = *(const unsigned*)&sAh[(rb+g  )*40 + kt*16 + kq];
                ah[mt][1] = *(const unsigned*)&sAh[(rb+g+8)*40 + kt*16 + kq];
                ah[mt][2] = *(const unsigned*)&sAh[(rb+g  )*40 + kt*16 + kq + 8];
                ah[mt][3] = *(const unsigned*)&sAh[(rb+g+8)*40 + kt*16 + kq + 8];
                al[mt][0] = *(const unsigned*)&sAl[(rb+g  )*40 + kt*16 + kq];
                al[mt][1] = *(const unsigned*)&sAl[(rb+g+8)*40 + kt*16 + kq];
                al[mt][2] = *(const unsigned*)&sAl[(rb+g  )*40 + kt*16 + kq + 8];
                al[mt][3] = *(const unsigned*)&sAl[(rb+g+8)*40 + kt*16 + kq + 8];
            }
#pragma unroll
            for (int nt = 0; nt < 8; nt++) {
                int rn = wn*64 + nt*8 + g;
                unsigned bh[2], bl[2];
                bh[0] = *(const unsigned*)&sBh[rn*40 + kt*16 + kq];
                bh[1] = *(const unsigned*)&sBh[rn*40 + kt*16 + kq + 8];
                bl[0] = *(const unsigned*)&sBl[rn*40 + kt*16 + kq];
                bl[1] = *(const unsigned*)&sBl[rn*40 + kt*16 + kq + 8];
#pragma unroll
                for (int mt = 0; mt < 2; mt++) {
                    mma16816(c[mt][nt], ah[mt], bh);
                    mma16816(c[mt][nt], al[mt], bh);
                    mma16816(c[mt][nt], ah[mt], bl);
                }
            }
        }
        __syncthreads();
    }

#pragma unroll
    for (int mt = 0; mt < 2; mt++) {
        int r0 = m0 + wm*32 + mt*16 + g;
#pragma unroll
        for (int nt = 0; nt < 8; nt++) {
            int col = n0 + wn*64 + nt*8 + kq;
            if (SPLIT) {
                *(unsigned*)&outH[(size_t)r0*D_ + col]     = pack_bf16x2(c[mt][nt][0], c[mt][nt][1]);
                *(unsigned*)&outH[(size_t)(r0+8)*D_ + col] = pack_bf16x2(c[mt][nt][2], c[mt][nt][3]);
            } else {
                *(float2*)&outF[(size_t)r0*D_ + col] = make_float2(c[mt][nt][0], c[mt][nt][1]);
                *(float2*)&outF[(size_t)(r0+8)*D_ + col] = make_float2(c[mt][nt][2], c[mt][nt][3]);
            }
        }
    }
}

// ---------------------------------------------------------------------------
// Kernel 4: flash attention, online softmax.
// S = QK^T in SINGLE bf16 (scores ~3.6e-4 + fp32 bias; rounding error ~1e-6).
// P.V keeps 3-product hi/lo.
// ---------------------------------------------------------------------------
#define AKH 0                          // K bf16 [256][40] = 20480 B
#define AVH 20480                      // V^T hi [32][264] = 16896 B
#define AVL 37376                      // V^T lo
#define ABI 54272                      // 256 f32
#define ASM_TOT 55296
#define KP  40
#define VP  264

__global__ void __launch_bounds__(256, 2)
attn_kernel(const float* __restrict__ ehr_times, const float* __restrict__ itv) {
    extern __shared__ char sm[];
    int tid = threadIdx.x;
    int wid = tid >> 5, lane = tid & 31;
    int g  = lane >> 2;
    int kq = (lane & 3) * 2;
    int h    = blockIdx.x;
    int half = blockIdx.y;
    int bp   = blockIdx.z;
    int b = bp >> 5;

    {
        const __nv_bfloat16* kh = g_kh + (size_t)(b*L_)*D_ + h*HD_;
        for (int idx = tid; idx < 2048; idx += 256) {
            int r = idx >> 3, c4 = (idx & 7) * 4;
            *(uint2*)(sm + AKH + r*(KP*2) + c4*2) = *(const uint2*)(kh + r*D_ + c4);
        }
    }
    {
        const __nv_bfloat16* vh = g_vth + (size_t)(b*D_ + h*HD_)*L_;
        const __nv_bfloat16* vl = g_vtl + (size_t)(b*D_ + h*HD_)*L_;
        for (int idx = tid; idx < 1024; idx += 256) {
            int hd = idx >> 5, c8 = (idx & 31) * 8;
            *(uint4*)(sm + AVH + hd*(VP*2) + c8*2) = *(const uint4*)(vh + hd*L_ + c8);
            *(uint4*)(sm + AVL + hd*(VP*2) + c8*2) = *(const uint4*)(vl + hd*L_ + c8);
        }
    }
    {
        float s = itv[bp*2 + 0];
        float e = itv[bp*2 + 1];
        float ctr = 0.5f*(s+e);
        float t = ehr_times[b*L_ + tid];
        ((float*)(sm + ABI))[tid] = (t >= s && t <= e) ? -fabsf(t - ctr) : -1e30f;
    }

    unsigned qah[2][4];
    {
        size_t qrow = (size_t)bp*L_ + half*128 + wid*16;
#pragma unroll
        for (int kt = 0; kt < 2; kt++) {
            size_t base = (qrow + g)*D_ + h*HD_ + kt*16 + kq;
            qah[kt][0] = *(const unsigned*)(g_qh + base);
            qah[kt][1] = *(const unsigned*)(g_qh + base + 8*D_);
            qah[kt][2] = *(const unsigned*)(g_qh + base + 8);
            qah[kt][3] = *(const unsigned*)(g_qh + base + 8*D_ + 8);
        }
    }
    __syncthreads();

    const float* sb = (const float*)(sm + ABI);
    float m0 = -1e30f, m1 = -1e30f, d0 = 0.f, d1 = 0.f;
    float o[4][4];
#pragma unroll
    for (int nt = 0; nt < 4; nt++) { o[nt][0]=0.f; o[nt][1]=0.f; o[nt][2]=0.f; o[nt][3]=0.f; }

#pragma unroll 1
    for (int ch = 0; ch < 4; ch++) {
        // ---- S chunk = Q K^T (single bf16 product) ----
        float c[8][4];
#pragma unroll
        for (int nt = 0; nt < 8; nt++) { c[nt][0]=0.f; c[nt][1]=0.f; c[nt][2]=0.f; c[nt][3]=0.f; }
#pragma unroll
        for (int nt = 0; nt < 8; nt++) {
            const char* kb = sm + AKH + (ch*64 + nt*8 + g)*(KP*2);
#pragma unroll
            for (int kt = 0; kt < 2; kt++) {
                unsigned bh[2];
                bh[0] = *(const unsigned*)(kb + (kt*16 + kq)*2);
                bh[1] = *(const unsigned*)(kb + (kt*16 + kq)*2 + 16);
                mma16816(c[nt], qah[kt], bh);
            }
        }
        // ---- add bias + chunk max ----
        float cm0 = -1e30f, cm1 = -1e30f;
#pragma unroll
        for (int nt = 0; nt < 8; nt++) {
            float2 bb = *(const float2*)&sb[ch*64 + nt*8 + kq];
            c[nt][0] += bb.x; c[nt][1] += bb.y;
            c[nt][2] += bb.x; c[nt][3] += bb.y;
            cm0 = fmaxf(cm0, fmaxf(c[nt][0], c[nt][1]));
            cm1 = fmaxf(cm1, fmaxf(c[nt][2], c[nt][3]));
        }
        cm0 = fmaxf(cm0, __shfl_xor_sync(0xffffffffu, cm0, 1));
        cm0 = fmaxf(cm0, __shfl_xor_sync(0xffffffffu, cm0, 2));
        cm1 = fmaxf(cm1, __shfl_xor_sync(0xffffffffu, cm1, 1));
        cm1 = fmaxf(cm1, __shfl_xor_sync(0xffffffffu, cm1, 2));
        // ---- online rescale ----
        float nm0 = fmaxf(m0, cm0), nm1 = fmaxf(m1, cm1);
        float corr0 = __expf(m0 - nm0), corr1 = __expf(m1 - nm1);
        m0 = nm0; m1 = nm1;
        d0 *= corr0; d1 *= corr1;
#pragma unroll
        for (int nt = 0; nt < 4; nt++) {
            o[nt][0] *= corr0; o[nt][1] *= corr0;
            o[nt][2] *= corr1; o[nt][3] *= corr1;
        }
        // ---- exp + den partials ----
#pragma unroll
        for (int nt = 0; nt < 8; nt++) {
            c[nt][0] = __expf(c[nt][0] - m0);
            c[nt][1] = __expf(c[nt][1] - m0);
            c[nt][2] = __expf(c[nt][2] - m1);
            c[nt][3] = __expf(c[nt][3] - m1);
            d0 += c[nt][0] + c[nt][1];
            d1 += c[nt][2] + c[nt][3];
        }
        // ---- O += P_chunk * V_chunk (3-product hi/lo) ----
#pragma unroll
        for (int kt = 0; kt < 4; kt++) {
            unsigned ah[4], al[4];
            split2(c[2*kt][0],   c[2*kt][1],   ah[0], al[0]);
            split2(c[2*kt][2],   c[2*kt][3],   ah[1], al[1]);
            split2(c[2*kt+1][0], c[2*kt+1][1], ah[2], al[2]);
            split2(c[2*kt+1][2], c[2*kt+1][3], ah[3], al[3]);
#pragma unroll
            for (int nt = 0; nt < 4; nt++) {
                const char* vb = sm + (nt*8 + g)*(VP*2) + (ch*64 + kt*16 + kq)*2;
                unsigned bh[2], bl[2];
                bh[0] = *(const unsigned*)(vb + AVH);
                bh[1] = *(const unsigned*)(vb + AVH + 16);
                bl[0] = *(const unsigned*)(vb + AVL);
                bl[1] = *(const unsigned*)(vb + AVL + 16);
                mma16816(o[nt], ah, bh);
                mma16816(o[nt], al, bh);
                mma16816(o[nt], ah, bl);
            }
        }
    }

    // ---- reduce den partials across the quad ----
    d0 += __shfl_xor_sync(0xffffffffu, d0, 1);
    d0 += __shfl_xor_sync(0xffffffffu, d0, 2);
    d1 += __shfl_xor_sync(0xffffffffu, d1, 1);
    d1 += __shfl_xor_sync(0xffffffffu, d1, 2);

    // ---- epilogue: normalize, split, store ctx ----
    {
        float inv0 = 1.f / d0, inv1 = 1.f / d1;
        size_t orow = (size_t)bp*L_ + half*128 + wid*16;
#pragma unroll
        for (int nt = 0; nt < 4; nt++) {
            unsigned h0, l0, h1, l1;
            split2(o[nt][0]*inv0, o[nt][1]*inv0, h0, l0);
            split2(o[nt][2]*inv1, o[nt][3]*inv1, h1, l1);
            size_t i0 = (orow+g  )*D_ + h*HD_ + nt*8 + kq;
            size_t i1 = (orow+g+8)*D_ + h*HD_ + nt*8 + kq;
            *(unsigned*)&g_ctxh[i0] = h0;
            *(unsigned*)&g_ctxl[i0] = l0;
            *(unsigned*)&g_ctxh[i1] = h1;
            *(unsigned*)&g_ctxl[i1] = l1;
        }
    }
}

// ---------------------------------------------------------------------------
extern "C" void kernel_launch(void* const* d_in, const int* in_sizes, int n_in,
                              void* d_out, int out_size) {
    const float* ehr       = (const float*)d_in[0];
    const float* ehr_times = (const float*)d_in[1];
    const float* itv       = (const float*)d_in[2];
    const float* w1        = (const float*)d_in[3];
    const float* b1        = (const float*)d_in[4];
    const float* w2        = (const float*)d_in[5];
    const float* b2        = (const float*)d_in[6];
    const float* wq        = (const float*)d_in[7];
    const float* bq        = (const float*)d_in[8];
    const float* wk        = (const float*)d_in[9];
    const float* bk        = (const float*)d_in[10];
    const float* wv        = (const float*)d_in[11];
    const float* bv        = (const float*)d_in[12];
    const float* wo        = (const float*)d_in[13];
    const float* bo        = (const float*)d_in[14];
    float* out = (float*)d_out;

    __nv_bfloat16 *p_hh, *p_hl, *p_w2qTh, *p_w2qTl, *p_qh;
    __nv_bfloat16 *p_ctxh, *p_ctxl, *p_woTh, *p_woTl;
    float *p_bq2;
    cudaGetSymbolAddress((void**)&p_hh, g_hh);
    cudaGetSymbolAddress((void**)&p_hl, g_hl);
    cudaGetSymbolAddress((void**)&p_w2qTh, g_w2qTh);
    cudaGetSymbolAddress((void**)&p_w2qTl, g_w2qTl);
    cudaGetSymbolAddress((void**)&p_qh, g_qh);
    cudaGetSymbolAddress((void**)&p_ctxh, g_ctxh);
    cudaGetSymbolAddress((void**)&p_ctxl, g_ctxl);
    cudaGetSymbolAddress((void**)&p_woTh, g_woTh);
    cudaGetSymbolAddress((void**)&p_woTl, g_woTl);
    cudaGetSymbolAddress((void**)&p_bq2, g_bq2);

    fuse_w_kernel<<<DH_, D_>>>(w2, wq, b2, bq);
    prep_split_kernel<<<D_, D_>>>(wo);
    kv_kernel<<<B_*L_/8, 256>>>(ehr, wk, bk, wv, bv);
    h_kernel<<<B_*P_*L_/32, 256>>>(ehr_times, itv, w1, b1);

    // q = h @ W2q' (+bq2'), single-bf16 out
    gemm_kernel<DH_, true><<<dim3(256, 2), 256>>>(
        p_hh, p_hl, p_w2qTh, p_w2qTl, p_bq2, nullptr, p_qh);

    cudaFuncSetAttribute(attn_kernel, cudaFuncAttributeMaxDynamicSharedMemorySize, ASM_TOT);
    attn_kernel<<<dim3(H_, 2, B_*P_), 256, ASM_TOT>>>(ehr_times, itv);

    // out = ctx @ wo + bo, fp32 out
    gemm_kernel<D_, false><<<dim3(256, 2), 256>>>(
        p_ctxh, p_ctxl, p_woTh, p_woTl, bo, out, nullptr);
}

// round 12
// speedup vs baseline: 1.2551x; 1.0145x over previous
#include <cuda_runtime.h>
#include <cuda_bf16.h>
#include <math.h>
#include <cstdint>

#define B_  4
#define L_  256
#define D_  256
#define P_  32
#define H_  8
#define HD_ 32
#define DH_ 128   // D/2

// ======================= mma.sync bf16 =====================================
__device__ __forceinline__ void mma16816(float* c, const unsigned* a, const unsigned* b) {
    asm volatile("mma.sync.aligned.m16n8k16.row.col.f32.bf16.bf16.f32 "
        "{%0,%1,%2,%3}, {%4,%5,%6,%7}, {%8,%9}, {%0,%1,%2,%3};"
        : "+f"(c[0]), "+f"(c[1]), "+f"(c[2]), "+f"(c[3])
        : "r"(a[0]), "r"(a[1]), "r"(a[2]), "r"(a[3]), "r"(b[0]), "r"(b[1]));
}
__device__ __forceinline__ void split2(float x0, float x1, unsigned& whi, unsigned& wlo) {
    __nv_bfloat16 h0 = __float2bfloat16(x0);
    __nv_bfloat16 h1 = __float2bfloat16(x1);
    __nv_bfloat16 l0 = __float2bfloat16(x0 - __bfloat162float(h0));
    __nv_bfloat16 l1 = __float2bfloat16(x1 - __bfloat162float(h1));
    whi = (unsigned)*(unsigned short*)&h0 | ((unsigned)*(unsigned short*)&h1 << 16);
    wlo = (unsigned)*(unsigned short*)&l0 | ((unsigned)*(unsigned short*)&l1 << 16);
}
__device__ __forceinline__ unsigned pack_bf16x2(float x0, float x1) {
    __nv_bfloat162 t = __floats2bfloat162_rn(x0, x1);
    return *reinterpret_cast<unsigned*>(&t);
}
__device__ __forceinline__ void split1(float x, __nv_bfloat16& h, __nv_bfloat16& l) {
    h = __float2bfloat16(x);
    l = __float2bfloat16(x - __bfloat162float(h));
}

// ======================= scratch =========================================
__device__ __nv_bfloat16 g_eh[B_*L_*D_];        // ehr hi
__device__ __nv_bfloat16 g_el[B_*L_*D_];        // ehr lo
__device__ __nv_bfloat16 g_kh[B_*L_*D_];        // K single bf16
__device__ __nv_bfloat16 g_vh[B_*L_*D_];        // V hi, row-major
__device__ __nv_bfloat16 g_vl[B_*L_*D_];        // V lo, row-major
__device__ __nv_bfloat16 g_qh[B_*P_*L_*D_];     // q single bf16
__device__ __nv_bfloat16 g_ctxh[B_*P_*L_*D_];
__device__ __nv_bfloat16 g_ctxl[B_*P_*L_*D_];
__device__ __nv_bfloat16 g_hh[B_*P_*L_*DH_];
__device__ __nv_bfloat16 g_hl[B_*P_*L_*DH_];
__device__ __nv_bfloat16 g_woTh[D_*D_];         // [n][k]
__device__ __nv_bfloat16 g_woTl[D_*D_];
__device__ __nv_bfloat16 g_wkT[D_*D_];          // [n][k] single bf16
__device__ __nv_bfloat16 g_wvTh[D_*D_];         // [n][k]
__device__ __nv_bfloat16 g_wvTl[D_*D_];
__device__ __nv_bfloat16 g_w2qTh[D_*DH_];       // [n][k], scale folded
__device__ __nv_bfloat16 g_w2qTl[D_*DH_];
__device__ float g_W2q[DH_*D_];
__device__ float g_bq2[D_];                     // scale folded

// ---------------------------------------------------------------------------
// Kernel 1: W2q = w2 @ wq, bq2 = scale*(b2 @ wq + bq)
// ---------------------------------------------------------------------------
__global__ void fuse_w_kernel(const float* __restrict__ w2, const float* __restrict__ wq,
                              const float* __restrict__ b2, const float* __restrict__ bq) {
    int j = blockIdx.x, c = threadIdx.x;
    float acc = 0.f;
    for (int k = 0; k < D_; k++) acc = fmaf(w2[j*D_+k], wq[k*D_+c], acc);
    g_W2q[j*D_+c] = acc;
    if (j == 0) {
        float a = 0.f;
        for (int k = 0; k < D_; k++) a = fmaf(b2[k], wq[k*D_+c], a);
        g_bq2[c] = 0.17677669529663687f * (a + bq[c]);
    }
}

// ---------------------------------------------------------------------------
// Kernel 1b: transpose+split weights: wo (hi/lo), scale*W2q (hi/lo),
//            wk (single), wv (hi/lo).  grid 256 = n, block 256 = k
// ---------------------------------------------------------------------------
__global__ void prep_split_kernel(const float* __restrict__ wo,
                                  const float* __restrict__ wk,
                                  const float* __restrict__ wv) {
    int n = blockIdx.x, k = threadIdx.x;
    __nv_bfloat16 h, l;
    split1(wo[k*D_ + n], h, l);
    g_woTh[n*D_ + k] = h;
    g_woTl[n*D_ + k] = l;
    g_wkT[n*D_ + k] = __float2bfloat16(wk[k*D_ + n]);
    split1(wv[k*D_ + n], h, l);
    g_wvTh[n*D_ + k] = h;
    g_wvTl[n*D_ + k] = l;
    if (k < DH_) {
        split1(0.17677669529663687f * g_W2q[k*D_ + n], h, l);
        g_w2qTh[n*DH_ + k] = h;
        g_w2qTl[n*DH_ + k] = l;
    }
}

// ---------------------------------------------------------------------------
// Kernel 1c: split ehr into hi/lo bf16
// ---------------------------------------------------------------------------
__global__ void split_ehr_kernel(const float* __restrict__ ehr) {
    int i = blockIdx.x * 256 + threadIdx.x;
    __nv_bfloat16 h, l;
    split1(ehr[i], h, l);
    g_eh[i] = h;
    g_el[i] = l;
}

// ---------------------------------------------------------------------------
// Kernel 3: time features -> MLP -> gelu -> h (split bf16)
// ---------------------------------------------------------------------------
__global__ void h_kernel(const float* __restrict__ ehr_times, const float* __restrict__ itv,
                         const float* __restrict__ w1, const float* __restrict__ b1) {
    __shared__ float3 stf[32];
    int tid = threadIdx.x;
    int g0 = blockIdx.x * 32;
    int b  = g0 / (P_*L_);
    int p  = (g0 / L_) % P_;
    int l0 = g0 % L_;
    if (tid < 32) {
        float t = ehr_times[b*L_ + l0 + tid];
        float s = itv[(b*P_+p)*2 + 0];
        float e = itv[(b*P_+p)*2 + 1];
        float ds = t - s, de = e - t;
        float x  = ds * de;
        float sg = 1.f / (1.f + expf(-x));
        stf[tid] = make_float3(ds, de, sg);
    }
    __syncthreads();
    for (int i = tid; i < 32*DH_; i += 256) {
        int r = i >> 7, j = i & 127;
        float3 tf = stf[r];
        float z = tf.x*w1[j] + tf.y*w1[DH_+j] + tf.z*w1[2*DH_+j] + b1[j];
        float v = 0.5f * z * (1.f + erff(z * 0.70710678118654752f));
        __nv_bfloat16 h, l;
        split1(v, h, l);
        g_hh[(size_t)g0*DH_ + i] = h;
        g_hl[(size_t)g0*DH_ + i] = l;
    }
}

// ---------------------------------------------------------------------------
// Generic bf16 GEMM. PROD3: hi/lo 3-product (else single-product, hi only).
// OM: 0 = fp32 out, 1 = single bf16 out, 2 = split bf16 hi/lo out.
// ---------------------------------------------------------------------------
template<int K, bool PROD3, int OM>
__global__ void __launch_bounds__(256)
gemm_kernel(const __nv_bfloat16* __restrict__ Ah, const __nv_bfloat16* __restrict__ Al,
            const __nv_bfloat16* __restrict__ BTh, const __nv_bfloat16* __restrict__ BTl,
            const float* __restrict__ bias,
            float* __restrict__ outF,
            __nv_bfloat16* __restrict__ outH, __nv_bfloat16* __restrict__ outL) {
    __shared__ __nv_bfloat16 sAh[128*40], sAl[128*40], sBh[128*40], sBl[128*40];
    int tid = threadIdx.x, wid = tid >> 5, lane = tid & 31;
    int g = lane >> 2, kq = (lane & 3) * 2;
    int wm = wid & 3, wn = wid >> 2;
    int m0 = blockIdx.x * 128, n0 = blockIdx.y * 128;

    float c[2][8][4];
#pragma unroll
    for (int nt = 0; nt < 8; nt++) {
        float2 bb = *(const float2*)&bias[n0 + wn*64 + nt*8 + kq];
#pragma unroll
        for (int mt = 0; mt < 2; mt++) {
            c[mt][nt][0] = bb.x; c[mt][nt][1] = bb.y;
            c[mt][nt][2] = bb.x; c[mt][nt][3] = bb.y;
        }
    }

    for (int kc = 0; kc < K; kc += 32) {
        for (int idx = tid; idx < 1024; idx += 256) {
            int r = idx >> 3, c4 = (idx & 7) * 4;
            *(uint2*)&sAh[r*40 + c4] = *(const uint2*)&Ah[(size_t)(m0+r)*K + kc + c4];
            *(uint2*)&sBh[r*40 + c4] = *(const uint2*)&BTh[(size_t)(n0+r)*K + kc + c4];
            if (PROD3) {
                *(uint2*)&sAl[r*40 + c4] = *(const uint2*)&Al[(size_t)(m0+r)*K + kc + c4];
                *(uint2*)&sBl[r*40 + c4] = *(const uint2*)&BTl[(size_t)(n0+r)*K + kc + c4];
            }
        }
        __syncthreads();
#pragma unroll
        for (int kt = 0; kt < 2; kt++) {
            unsigned ah[2][4], al[2][4];
#pragma unroll
            for (int mt = 0; mt < 2; mt++) {
                int rb = wm*32 + mt*16;
                ah[mt][0] = *(const unsigned*)&sAh[(rb+g  )*40 + kt*16 + kq];
                ah[mt][1] = *(const unsigned*)&sAh[(rb+g+8)*40 + kt*16 + kq];
                ah[mt][2] = *(const unsigned*)&sAh[(rb+g  )*40 + kt*16 + kq + 8];
                ah[mt][3] = *(const unsigned*)&sAh[(rb+g+8)*40 + kt*16 + kq + 8];
                if (PROD3) {
                    al[mt][0] = *(const unsigned*)&sAl[(rb+g  )*40 + kt*16 + kq];
                    al[mt][1] = *(const unsigned*)&sAl[(rb+g+8)*40 + kt*16 + kq];
                    al[mt][2] = *(const unsigned*)&sAl[(rb+g  )*40 + kt*16 + kq + 8];
                    al[mt][3] = *(const unsigned*)&sAl[(rb+g+8)*40 + kt*16 + kq + 8];
                }
            }
#pragma unroll
            for (int nt = 0; nt < 8; nt++) {
                int rn = wn*64 + nt*8 + g;
                unsigned bh[2], bl[2];
                bh[0] = *(const unsigned*)&sBh[rn*40 + kt*16 + kq];
                bh[1] = *(const unsigned*)&sBh[rn*40 + kt*16 + kq + 8];
                if (PROD3) {
                    bl[0] = *(const unsigned*)&sBl[rn*40 + kt*16 + kq];
                    bl[1] = *(const unsigned*)&sBl[rn*40 + kt*16 + kq + 8];
                }
#pragma unroll
                for (int mt = 0; mt < 2; mt++) {
                    mma16816(c[mt][nt], ah[mt], bh);
                    if (PROD3) {
                        mma16816(c[mt][nt], al[mt], bh);
                        mma16816(c[mt][nt], ah[mt], bl);
                    }
                }
            }
        }
        __syncthreads();
    }

#pragma unroll
    for (int mt = 0; mt < 2; mt++) {
        int r0 = m0 + wm*32 + mt*16 + g;
#pragma unroll
        for (int nt = 0; nt < 8; nt++) {
            int col = n0 + wn*64 + nt*8 + kq;
            if (OM == 0) {
                *(float2*)&outF[(size_t)r0*D_ + col] = make_float2(c[mt][nt][0], c[mt][nt][1]);
                *(float2*)&outF[(size_t)(r0+8)*D_ + col] = make_float2(c[mt][nt][2], c[mt][nt][3]);
            } else if (OM == 1) {
                *(unsigned*)&outH[(size_t)r0*D_ + col]     = pack_bf16x2(c[mt][nt][0], c[mt][nt][1]);
                *(unsigned*)&outH[(size_t)(r0+8)*D_ + col] = pack_bf16x2(c[mt][nt][2], c[mt][nt][3]);
            } else {
                unsigned h0, l0, h1, l1;
                split2(c[mt][nt][0], c[mt][nt][1], h0, l0);
                split2(c[mt][nt][2], c[mt][nt][3], h1, l1);
                *(unsigned*)&outH[(size_t)r0*D_ + col] = h0;
                *(unsigned*)&outL[(size_t)r0*D_ + col] = l0;
                *(unsigned*)&outH[(size_t)(r0+8)*D_ + col] = h1;
                *(unsigned*)&outL[(size_t)(r0+8)*D_ + col] = l1;
            }
        }
    }
}

// ---------------------------------------------------------------------------
// Kernel 4: flash attention (R11 core). V^T tile transposed from row-major V.
// ---------------------------------------------------------------------------
#define AKH 0                          // K bf16 [256][40] = 20480 B
#define AVH 20480                      // V^T hi [32][264] = 16896 B
#define AVL 37376                      // V^T lo
#define ABI 54272                      // 256 f32
#define ASM_TOT 55296
#define KP  40
#define VP  264

__global__ void __launch_bounds__(256, 2)
attn_kernel(const float* __restrict__ ehr_times, const float* __restrict__ itv) {
    extern __shared__ char sm[];
    int tid = threadIdx.x;
    int wid = tid >> 5, lane = tid & 31;
    int g  = lane >> 2;
    int kq = (lane & 3) * 2;
    int h    = blockIdx.x;
    int half = blockIdx.y;
    int bp   = blockIdx.z;
    int b = bp >> 5;

    {
        const __nv_bfloat16* kh = g_kh + (size_t)(b*L_)*D_ + h*HD_;
        for (int idx = tid; idx < 2048; idx += 256) {
            int r = idx >> 3, c4 = (idx & 7) * 4;
            *(uint2*)(sm + AKH + r*(KP*2) + c4*2) = *(const uint2*)(kh + r*D_ + c4);
        }
    }
    {
        // V^T fill: transpose from row-major hi/lo V (L2-hot, reused 64x)
        const __nv_bfloat16* vh = g_vh + (size_t)(b*L_)*D_ + h*HD_;
        const __nv_bfloat16* vl = g_vl + (size_t)(b*L_)*D_ + h*HD_;
        for (int idx = tid; idx < 4096; idx += 256) {
            int l = idx >> 4, hd2 = idx & 15;
            unsigned wh = *(const unsigned*)(vh + (size_t)l*D_ + hd2*2);
            unsigned wl = *(const unsigned*)(vl + (size_t)l*D_ + hd2*2);
            *(unsigned short*)(sm + AVH + (hd2*2  )*(VP*2) + l*2) = (unsigned short)wh;
            *(unsigned short*)(sm + AVH + (hd2*2+1)*(VP*2) + l*2) = (unsigned short)(wh >> 16);
            *(unsigned short*)(sm + AVL + (hd2*2  )*(VP*2) + l*2) = (unsigned short)wl;
            *(unsigned short*)(sm + AVL + (hd2*2+1)*(VP*2) + l*2) = (unsigned short)(wl >> 16);
        }
    }
    {
        float s = itv[bp*2 + 0];
        float e = itv[bp*2 + 1];
        float ctr = 0.5f*(s+e);
        float t = ehr_times[b*L_ + tid];
        ((float*)(sm + ABI))[tid] = (t >= s && t <= e) ? -fabsf(t - ctr) : -1e30f;
    }

    unsigned qah[2][4];
    {
        size_t qrow = (size_t)bp*L_ + half*128 + wid*16;
#pragma unroll
        for (int kt = 0; kt < 2; kt++) {
            size_t base = (qrow + g)*D_ + h*HD_ + kt*16 + kq;
            qah[kt][0] = *(const unsigned*)(g_qh + base);
            qah[kt][1] = *(const unsigned*)(g_qh + base + 8*D_);
            qah[kt][2] = *(const unsigned*)(g_qh + base + 8);
            qah[kt][3] = *(const unsigned*)(g_qh + base + 8*D_ + 8);
        }
    }
    __syncthreads();

    const float* sb = (const float*)(sm + ABI);
    float m0 = -1e30f, m1 = -1e30f, d0 = 0.f, d1 = 0.f;
    float o[4][4];
#pragma unroll
    for (int nt = 0; nt < 4; nt++) { o[nt][0]=0.f; o[nt][1]=0.f; o[nt][2]=0.f; o[nt][3]=0.f; }

#pragma unroll 1
    for (int ch = 0; ch < 4; ch++) {
        float c[8][4];
#pragma unroll
        for (int nt = 0; nt < 8; nt++) { c[nt][0]=0.f; c[nt][1]=0.f; c[nt][2]=0.f; c[nt][3]=0.f; }
#pragma unroll
        for (int nt = 0; nt < 8; nt++) {
            const char* kb = sm + AKH + (ch*64 + nt*8 + g)*(KP*2);
#pragma unroll
            for (int kt = 0; kt < 2; kt++) {
                unsigned bh[2];
                bh[0] = *(const unsigned*)(kb + (kt*16 + kq)*2);
                bh[1] = *(const unsigned*)(kb + (kt*16 + kq)*2 + 16);
                mma16816(c[nt], qah[kt], bh);
            }
        }
        float cm0 = -1e30f, cm1 = -1e30f;
#pragma unroll
        for (int nt = 0; nt < 8; nt++) {
            float2 bb = *(const float2*)&sb[ch*64 + nt*8 + kq];
            c[nt][0] += bb.x; c[nt][1] += bb.y;
            c[nt][2] += bb.x; c[nt][3] += bb.y;
            cm0 = fmaxf(cm0, fmaxf(c[nt][0], c[nt][1]));
            cm1 = fmaxf(cm1, fmaxf(c[nt][2], c[nt][3]));
        }
        cm0 = fmaxf(cm0, __shfl_xor_sync(0xffffffffu, cm0, 1));
        cm0 = fmaxf(cm0, __shfl_xor_sync(0xffffffffu, cm0, 2));
        cm1 = fmaxf(cm1, __shfl_xor_sync(0xffffffffu, cm1, 1));
        cm1 = fmaxf(cm1, __shfl_xor_sync(0xffffffffu, cm1, 2));
        float nm0 = fmaxf(m0, cm0), nm1 = fmaxf(m1, cm1);
        float corr0 = __expf(m0 - nm0), corr1 = __expf(m1 - nm1);
        m0 = nm0; m1 = nm1;
        d0 *= corr0; d1 *= corr1;
#pragma unroll
        for (int nt = 0; nt < 4; nt++) {
            o[nt][0] *= corr0; o[nt][1] *= corr0;
            o[nt][2] *= corr1; o[nt][3] *= corr1;
        }
#pragma unroll
        for (int nt = 0; nt < 8; nt++) {
            c[nt][0] = __expf(c[nt][0] - m0);
            c[nt][1] = __expf(c[nt][1] - m0);
            c[nt][2] = __expf(c[nt][2] - m1);
            c[nt][3] = __expf(c[nt][3] - m1);
            d0 += c[nt][0] + c[nt][1];
            d1 += c[nt][2] + c[nt][3];
        }
#pragma unroll
        for (int kt = 0; kt < 4; kt++) {
            unsigned ah[4], al[4];
            split2(c[2*kt][0],   c[2*kt][1],   ah[0], al[0]);
            split2(c[2*kt][2],   c[2*kt][3],   ah[1], al[1]);
            split2(c[2*kt+1][0], c[2*kt+1][1], ah[2], al[2]);
            split2(c[2*kt+1][2], c[2*kt+1][3], ah[3], al[3]);
#pragma unroll
            for (int nt = 0; nt < 4; nt++) {
                const char* vb = sm + (nt*8 + g)*(VP*2) + (ch*64 + kt*16 + kq)*2;
                unsigned bh[2], bl[2];
                bh[0] = *(const unsigned*)(vb + AVH);
                bh[1] = *(const unsigned*)(vb + AVH + 16);
                bl[0] = *(const unsigned*)(vb + AVL);
                bl[1] = *(const unsigned*)(vb + AVL + 16);
                mma16816(o[nt], ah, bh);
                mma16816(o[nt], al, bh);
                mma16816(o[nt], ah, bl);
            }
        }
    }

    d0 += __shfl_xor_sync(0xffffffffu, d0, 1);
    d0 += __shfl_xor_sync(0xffffffffu, d0, 2);
    d1 += __shfl_xor_sync(0xffffffffu, d1, 1);
    d1 += __shfl_xor_sync(0xffffffffu, d1, 2);

    {
        float inv0 = 1.f / d0, inv1 = 1.f / d1;
        size_t orow = (size_t)bp*L_ + half*128 + wid*16;
#pragma unroll
        for (int nt = 0; nt < 4; nt++) {
            unsigned h0, l0, h1, l1;
            split2(o[nt][0]*inv0, o[nt][1]*inv0, h0, l0);
            split2(o[nt][2]*inv1, o[nt][3]*inv1, h1, l1);
            size_t i0 = (orow+g  )*D_ + h*HD_ + nt*8 + kq;
            size_t i1 = (orow+g+8)*D_ + h*HD_ + nt*8 + kq;
            *(unsigned*)&g_ctxh[i0] = h0;
            *(unsigned*)&g_ctxl[i0] = l0;
            *(unsigned*)&g_ctxh[i1] = h1;
            *(unsigned*)&g_ctxl[i1] = l1;
        }
    }
}

// ---------------------------------------------------------------------------
extern "C" void kernel_launch(void* const* d_in, const int* in_sizes, int n_in,
                              void* d_out, int out_size) {
    const float* ehr       = (const float*)d_in[0];
    const float* ehr_times = (const float*)d_in[1];
    const float* itv       = (const float*)d_in[2];
    const float* w1        = (const float*)d_in[3];
    const float* b1        = (const float*)d_in[4];
    const float* w2        = (const float*)d_in[5];
    const float* b2        = (const float*)d_in[6];
    const float* wq        = (const float*)d_in[7];
    const float* bq        = (const float*)d_in[8];
    const float* wk        = (const float*)d_in[9];
    const float* bk        = (const float*)d_in[10];
    const float* wv        = (const float*)d_in[11];
    const float* bv        = (const float*)d_in[12];
    const float* wo        = (const float*)d_in[13];
    const float* bo        = (const float*)d_in[14];
    float* out = (float*)d_out;

    __nv_bfloat16 *p_eh, *p_el, *p_kh, *p_vh, *p_vl, *p_qh;
    __nv_bfloat16 *p_hh, *p_hl, *p_w2qTh, *p_w2qTl;
    __nv_bfloat16 *p_ctxh, *p_ctxl, *p_woTh, *p_woTl;
    __nv_bfloat16 *p_wkT, *p_wvTh, *p_wvTl;
    float *p_bq2;
    cudaGetSymbolAddress((void**)&p_eh, g_eh);
    cudaGetSymbolAddress((void**)&p_el, g_el);
    cudaGetSymbolAddress((void**)&p_kh, g_kh);
    cudaGetSymbolAddress((void**)&p_vh, g_vh);
    cudaGetSymbolAddress((void**)&p_vl, g_vl);
    cudaGetSymbolAddress((void**)&p_qh, g_qh);
    cudaGetSymbolAddress((void**)&p_hh, g_hh);
    cudaGetSymbolAddress((void**)&p_hl, g_hl);
    cudaGetSymbolAddress((void**)&p_w2qTh, g_w2qTh);
    cudaGetSymbolAddress((void**)&p_w2qTl, g_w2qTl);
    cudaGetSymbolAddress((void**)&p_ctxh, g_ctxh);
    cudaGetSymbolAddress((void**)&p_ctxl, g_ctxl);
    cudaGetSymbolAddress((void**)&p_woTh, g_woTh);
    cudaGetSymbolAddress((void**)&p_woTl, g_woTl);
    cudaGetSymbolAddress((void**)&p_wkT, g_wkT);
    cudaGetSymbolAddress((void**)&p_wvTh, g_wvTh);
    cudaGetSymbolAddress((void**)&p_wvTl, g_wvTl);
    cudaGetSymbolAddress((void**)&p_bq2, g_bq2);

    fuse_w_kernel<<<DH_, D_>>>(w2, wq, b2, bq);
    prep_split_kernel<<<D_, D_>>>(wo, wk, wv);
    split_ehr_kernel<<<B_*L_, 256>>>(ehr);
    h_kernel<<<B_*P_*L_/32, 256>>>(ehr_times, itv, w1, b1);

    // K = ehr @ wk + bk  (single-product, single bf16 out)
    gemm_kernel<D_, false, 1><<<dim3(8, 2), 256>>>(
        p_eh, p_eh, p_wkT, p_wkT, bk, nullptr, p_kh, nullptr);
    // V = ehr @ wv + bv  (3-product, split hi/lo out)
    gemm_kernel<D_, true, 2><<<dim3(8, 2), 256>>>(
        p_eh, p_el, p_wvTh, p_wvTl, bv, nullptr, p_vh, p_vl);
    // q = h @ W2q' + bq2'  (3-product, single bf16 out)
    gemm_kernel<DH_, true, 1><<<dim3(256, 2), 256>>>(
        p_hh, p_hl, p_w2qTh, p_w2qTl, p_bq2, nullptr, p_qh, nullptr);

    cudaFuncSetAttribute(attn_kernel, cudaFuncAttributeMaxDynamicSharedMemorySize, ASM_TOT);
    attn_kernel<<<dim3(H_, 2, B_*P_), 256, ASM_TOT>>>(ehr_times, itv);

    // out = ctx @ wo + bo  (3-product, fp32 out)
    gemm_kernel<D_, true, 0><<<dim3(256, 2), 256>>>(
        p_ctxh, p_ctxl, p_woTh, p_woTl, bo, out, nullptr, nullptr);
}

// round 13
// speedup vs baseline: 1.3228x; 1.0540x over previous
#include <cuda_runtime.h>
#include <cuda_bf16.h>
#include <math.h>
#include <cstdint>

#define B_  4
#define L_  256
#define D_  256
#define P_  32
#define H_  8
#define HD_ 32
#define DH_ 128   // D/2

// ======================= mma.sync bf16 =====================================
__device__ __forceinline__ void mma16816(float* c, const unsigned* a, const unsigned* b) {
    asm volatile("mma.sync.aligned.m16n8k16.row.col.f32.bf16.bf16.f32 "
        "{%0,%1,%2,%3}, {%4,%5,%6,%7}, {%8,%9}, {%0,%1,%2,%3};"
        : "+f"(c[0]), "+f"(c[1]), "+f"(c[2]), "+f"(c[3])
        : "r"(a[0]), "r"(a[1]), "r"(a[2]), "r"(a[3]), "r"(b[0]), "r"(b[1]));
}
__device__ __forceinline__ unsigned pack_bf16x2(float x0, float x1) {
    __nv_bfloat162 t = __floats2bfloat162_rn(x0, x1);
    return *reinterpret_cast<unsigned*>(&t);
}
// fast split: hi = rn-rounded bf16 pair (1 cvt), lo from exact shift-expansion
__device__ __forceinline__ void split2(float x0, float x1, unsigned& whi, unsigned& wlo) {
    whi = pack_bf16x2(x0, x1);
    float h0 = __uint_as_float(whi << 16);
    float h1 = __uint_as_float(whi & 0xffff0000u);
    wlo = pack_bf16x2(x0 - h0, x1 - h1);
}
__device__ __forceinline__ void split1(float x, __nv_bfloat16& h, __nv_bfloat16& l) {
    h = __float2bfloat16(x);
    l = __float2bfloat16(x - __bfloat162float(h));
}

// ======================= scratch =========================================
__device__ __nv_bfloat16 g_eh[B_*L_*D_];        // ehr hi
__device__ __nv_bfloat16 g_el[B_*L_*D_];        // ehr lo
__device__ __nv_bfloat16 g_kh[B_*L_*D_];        // K single bf16
__device__ __nv_bfloat16 g_vh[B_*L_*D_];        // V hi, row-major
__device__ __nv_bfloat16 g_vl[B_*L_*D_];        // V lo, row-major
__device__ __nv_bfloat16 g_qh[B_*P_*L_*D_];     // q single bf16
__device__ __nv_bfloat16 g_ctxh[B_*P_*L_*D_];
__device__ __nv_bfloat16 g_ctxl[B_*P_*L_*D_];
__device__ __nv_bfloat16 g_hh[B_*P_*L_*DH_];
__device__ __nv_bfloat16 g_hl[B_*P_*L_*DH_];
__device__ __nv_bfloat16 g_woTh[D_*D_];         // [n][k]
__device__ __nv_bfloat16 g_woTl[D_*D_];
__device__ __nv_bfloat16 g_wkT[D_*D_];          // [n][k] single bf16
__device__ __nv_bfloat16 g_wvTh[D_*D_];         // [n][k]
__device__ __nv_bfloat16 g_wvTl[D_*D_];
__device__ __nv_bfloat16 g_w2qTh[D_*DH_];       // [n][k], scale folded
__device__ __nv_bfloat16 g_w2qTl[D_*DH_];
__device__ float g_W2q[DH_*D_];
__device__ float g_bq2[D_];                     // scale folded

// ---------------------------------------------------------------------------
// Kernel 1: W2q = w2 @ wq, bq2 = scale*(b2 @ wq + bq)
// ---------------------------------------------------------------------------
__global__ void fuse_w_kernel(const float* __restrict__ w2, const float* __restrict__ wq,
                              const float* __restrict__ b2, const float* __restrict__ bq) {
    int j = blockIdx.x, c = threadIdx.x;
    float acc = 0.f;
    for (int k = 0; k < D_; k++) acc = fmaf(w2[j*D_+k], wq[k*D_+c], acc);
    g_W2q[j*D_+c] = acc;
    if (j == 0) {
        float a = 0.f;
        for (int k = 0; k < D_; k++) a = fmaf(b2[k], wq[k*D_+c], a);
        g_bq2[c] = 0.17677669529663687f * (a + bq[c]);
    }
}

// ---------------------------------------------------------------------------
// Kernel 1b: transpose+split weights
// ---------------------------------------------------------------------------
__global__ void prep_split_kernel(const float* __restrict__ wo,
                                  const float* __restrict__ wk,
                                  const float* __restrict__ wv) {
    int n = blockIdx.x, k = threadIdx.x;
    __nv_bfloat16 h, l;
    split1(wo[k*D_ + n], h, l);
    g_woTh[n*D_ + k] = h;
    g_woTl[n*D_ + k] = l;
    g_wkT[n*D_ + k] = __float2bfloat16(wk[k*D_ + n]);
    split1(wv[k*D_ + n], h, l);
    g_wvTh[n*D_ + k] = h;
    g_wvTl[n*D_ + k] = l;
    if (k < DH_) {
        split1(0.17677669529663687f * g_W2q[k*D_ + n], h, l);
        g_w2qTh[n*DH_ + k] = h;
        g_w2qTl[n*DH_ + k] = l;
    }
}

// ---------------------------------------------------------------------------
// Kernel 1c: split ehr into hi/lo bf16
// ---------------------------------------------------------------------------
__global__ void split_ehr_kernel(const float* __restrict__ ehr) {
    int i = blockIdx.x * 256 + threadIdx.x;
    __nv_bfloat16 h, l;
    split1(ehr[i], h, l);
    g_eh[i] = h;
    g_el[i] = l;
}

// ---------------------------------------------------------------------------
// Kernel 3: time features -> MLP -> gelu -> h (split bf16)
// ---------------------------------------------------------------------------
__global__ void h_kernel(const float* __restrict__ ehr_times, const float* __restrict__ itv,
                         const float* __restrict__ w1, const float* __restrict__ b1) {
    __shared__ float3 stf[32];
    int tid = threadIdx.x;
    int g0 = blockIdx.x * 32;
    int b  = g0 / (P_*L_);
    int p  = (g0 / L_) % P_;
    int l0 = g0 % L_;
    if (tid < 32) {
        float t = ehr_times[b*L_ + l0 + tid];
        float s = itv[(b*P_+p)*2 + 0];
        float e = itv[(b*P_+p)*2 + 1];
        float ds = t - s, de = e - t;
        float x  = ds * de;
        float sg = 1.f / (1.f + expf(-x));
        stf[tid] = make_float3(ds, de, sg);
    }
    __syncthreads();
    for (int i = tid; i < 32*DH_; i += 256) {
        int r = i >> 7, j = i & 127;
        float3 tf = stf[r];
        float z = tf.x*w1[j] + tf.y*w1[DH_+j] + tf.z*w1[2*DH_+j] + b1[j];
        float v = 0.5f * z * (1.f + erff(z * 0.70710678118654752f));
        __nv_bfloat16 h, l;
        split1(v, h, l);
        g_hh[(size_t)g0*DH_ + i] = h;
        g_hl[(size_t)g0*DH_ + i] = l;
    }
}

// ---------------------------------------------------------------------------
// Generic bf16 GEMM. PROD3: hi/lo 3-product. OM: 0 fp32, 1 single bf16, 2 split.
// ---------------------------------------------------------------------------
template<int K, bool PROD3, int OM>
__global__ void __launch_bounds__(256)
gemm_kernel(const __nv_bfloat16* __restrict__ Ah, const __nv_bfloat16* __restrict__ Al,
            const __nv_bfloat16* __restrict__ BTh, const __nv_bfloat16* __restrict__ BTl,
            const float* __restrict__ bias,
            float* __restrict__ outF,
            __nv_bfloat16* __restrict__ outH, __nv_bfloat16* __restrict__ outL) {
    __shared__ __nv_bfloat16 sAh[128*40], sAl[128*40], sBh[128*40], sBl[128*40];
    int tid = threadIdx.x, wid = tid >> 5, lane = tid & 31;
    int g = lane >> 2, kq = (lane & 3) * 2;
    int wm = wid & 3, wn = wid >> 2;
    int m0 = blockIdx.x * 128, n0 = blockIdx.y * 128;

    float c[2][8][4];
#pragma unroll
    for (int nt = 0; nt < 8; nt++) {
        float2 bb = *(const float2*)&bias[n0 + wn*64 + nt*8 + kq];
#pragma unroll
        for (int mt = 0; mt < 2; mt++) {
            c[mt][nt][0] = bb.x; c[mt][nt][1] = bb.y;
            c[mt][nt][2] = bb.x; c[mt][nt][3] = bb.y;
        }
    }

    for (int kc = 0; kc < K; kc += 32) {
        for (int idx = tid; idx < 1024; idx += 256) {
            int r = idx >> 3, c4 = (idx & 7) * 4;
            *(uint2*)&sAh[r*40 + c4] = *(const uint2*)&Ah[(size_t)(m0+r)*K + kc + c4];
            *(uint2*)&sBh[r*40 + c4] = *(const uint2*)&BTh[(size_t)(n0+r)*K + kc + c4];
            if (PROD3) {
                *(uint2*)&sAl[r*40 + c4] = *(const uint2*)&Al[(size_t)(m0+r)*K + kc + c4];
                *(uint2*)&sBl[r*40 + c4] = *(const uint2*)&BTl[(size_t)(n0+r)*K + kc + c4];
            }
        }
        __syncthreads();
#pragma unroll
        for (int kt = 0; kt < 2; kt++) {
            unsigned ah[2][4], al[2][4];
#pragma unroll
            for (int mt = 0; mt < 2; mt++) {
                int rb = wm*32 + mt*16;
                ah[mt][0] = *(const unsigned*)&sAh[(rb+g  )*40 + kt*16 + kq];
                ah[mt][1] = *(const unsigned*)&sAh[(rb+g+8)*40 + kt*16 + kq];
                ah[mt][2] = *(const unsigned*)&sAh[(rb+g  )*40 + kt*16 + kq + 8];
                ah[mt][3] = *(const unsigned*)&sAh[(rb+g+8)*40 + kt*16 + kq + 8];
                if (PROD3) {
                    al[mt][0] = *(const unsigned*)&sAl[(rb+g  )*40 + kt*16 + kq];
                    al[mt][1] = *(const unsigned*)&sAl[(rb+g+8)*40 + kt*16 + kq];
                    al[mt][2] = *(const unsigned*)&sAl[(rb+g  )*40 + kt*16 + kq + 8];
                    al[mt][3] = *(const unsigned*)&sAl[(rb+g+8)*40 + kt*16 + kq + 8];
                }
            }
#pragma unroll
            for (int nt = 0; nt < 8; nt++) {
                int rn = wn*64 + nt*8 + g;
                unsigned bh[2], bl[2];
                bh[0] = *(const unsigned*)&sBh[rn*40 + kt*16 + kq];
                bh[1] = *(const unsigned*)&sBh[rn*40 + kt*16 + kq + 8];
                if (PROD3) {
                    bl[0] = *(const unsigned*)&sBl[rn*40 + kt*16 + kq];
                    bl[1] = *(const unsigned*)&sBl[rn*40 + kt*16 + kq + 8];
                }
#pragma unroll
                for (int mt = 0; mt < 2; mt++) {
                    mma16816(c[mt][nt], ah[mt], bh);
                    if (PROD3) {
                        mma16816(c[mt][nt], al[mt], bh);
                        mma16816(c[mt][nt], ah[mt], bl);
                    }
                }
            }
        }
        __syncthreads();
    }

#pragma unroll
    for (int mt = 0; mt < 2; mt++) {
        int r0 = m0 + wm*32 + mt*16 + g;
#pragma unroll
        for (int nt = 0; nt < 8; nt++) {
            int col = n0 + wn*64 + nt*8 + kq;
            if (OM == 0) {
                *(float2*)&outF[(size_t)r0*D_ + col] = make_float2(c[mt][nt][0], c[mt][nt][1]);
                *(float2*)&outF[(size_t)(r0+8)*D_ + col] = make_float2(c[mt][nt][2], c[mt][nt][3]);
            } else if (OM == 1) {
                *(unsigned*)&outH[(size_t)r0*D_ + col]     = pack_bf16x2(c[mt][nt][0], c[mt][nt][1]);
                *(unsigned*)&outH[(size_t)(r0+8)*D_ + col] = pack_bf16x2(c[mt][nt][2], c[mt][nt][3]);
            } else {
                unsigned h0, l0, h1, l1;
                split2(c[mt][nt][0], c[mt][nt][1], h0, l0);
                split2(c[mt][nt][2], c[mt][nt][3], h1, l1);
                *(unsigned*)&outH[(size_t)r0*D_ + col] = h0;
                *(unsigned*)&outL[(size_t)r0*D_ + col] = l0;
                *(unsigned*)&outH[(size_t)(r0+8)*D_ + col] = h1;
                *(unsigned*)&outL[(size_t)(r0+8)*D_ + col] = l1;
            }
        }
    }
}

// ---------------------------------------------------------------------------
// Kernel 4: flash attention WITHOUT max subtraction (m = 0).
// Scores s = q.k + bias, q.k ~ 4e-3, bias <= 0 -> exp(s) <= ~1.35, no overflow;
// masked: expf(-1e30) = 0. Softmax shift-invariance makes this exact.
// ---------------------------------------------------------------------------
#define AKH 0                          // K bf16 [256][40] = 20480 B
#define AVH 20480                      // V^T hi [32][264] = 16896 B
#define AVL 37376                      // V^T lo
#define ABI 54272                      // 256 f32
#define ASM_TOT 55296
#define KP  40
#define VP  264

__global__ void __launch_bounds__(256, 2)
attn_kernel(const float* __restrict__ ehr_times, const float* __restrict__ itv) {
    extern __shared__ char sm[];
    int tid = threadIdx.x;
    int wid = tid >> 5, lane = tid & 31;
    int g  = lane >> 2;
    int kq = (lane & 3) * 2;
    int h    = blockIdx.x;
    int half = blockIdx.y;
    int bp   = blockIdx.z;
    int b = bp >> 5;

    {
        const __nv_bfloat16* kh = g_kh + (size_t)(b*L_)*D_ + h*HD_;
        for (int idx = tid; idx < 2048; idx += 256) {
            int r = idx >> 3, c4 = (idx & 7) * 4;
            *(uint2*)(sm + AKH + r*(KP*2) + c4*2) = *(const uint2*)(kh + r*D_ + c4);
        }
    }
    {
        // V^T fill: transpose from row-major hi/lo V (L2-hot, reused 64x)
        const __nv_bfloat16* vh = g_vh + (size_t)(b*L_)*D_ + h*HD_;
        const __nv_bfloat16* vl = g_vl + (size_t)(b*L_)*D_ + h*HD_;
        for (int idx = tid; idx < 4096; idx += 256) {
            int l = idx >> 4, hd2 = idx & 15;
            unsigned wh = *(const unsigned*)(vh + (size_t)l*D_ + hd2*2);
            unsigned wl = *(const unsigned*)(vl + (size_t)l*D_ + hd2*2);
            *(unsigned short*)(sm + AVH + (hd2*2  )*(VP*2) + l*2) = (unsigned short)wh;
            *(unsigned short*)(sm + AVH + (hd2*2+1)*(VP*2) + l*2) = (unsigned short)(wh >> 16);
            *(unsigned short*)(sm + AVL + (hd2*2  )*(VP*2) + l*2) = (unsigned short)wl;
            *(unsigned short*)(sm + AVL + (hd2*2+1)*(VP*2) + l*2) = (unsigned short)(wl >> 16);
        }
    }
    {
        float s = itv[bp*2 + 0];
        float e = itv[bp*2 + 1];
        float ctr = 0.5f*(s+e);
        float t = ehr_times[b*L_ + tid];
        ((float*)(sm + ABI))[tid] = (t >= s && t <= e) ? -fabsf(t - ctr) : -1e30f;
    }

    unsigned qah[2][4];
    {
        size_t qrow = (size_t)bp*L_ + half*128 + wid*16;
#pragma unroll
        for (int kt = 0; kt < 2; kt++) {
            size_t base = (qrow + g)*D_ + h*HD_ + kt*16 + kq;
            qah[kt][0] = *(const unsigned*)(g_qh + base);
            qah[kt][1] = *(const unsigned*)(g_qh + base + 8*D_);
            qah[kt][2] = *(const unsigned*)(g_qh + base + 8);
            qah[kt][3] = *(const unsigned*)(g_qh + base + 8*D_ + 8);
        }
    }
    __syncthreads();

    const float* sb = (const float*)(sm + ABI);
    float d0 = 0.f, d1 = 0.f;
    float o[4][4];
#pragma unroll
    for (int nt = 0; nt < 4; nt++) { o[nt][0]=0.f; o[nt][1]=0.f; o[nt][2]=0.f; o[nt][3]=0.f; }

#pragma unroll 1
    for (int ch = 0; ch < 4; ch++) {
        // ---- S chunk = Q K^T (single bf16 product) ----
        float c[8][4];
#pragma unroll
        for (int nt = 0; nt < 8; nt++) { c[nt][0]=0.f; c[nt][1]=0.f; c[nt][2]=0.f; c[nt][3]=0.f; }
#pragma unroll
        for (int nt = 0; nt < 8; nt++) {
            const char* kb = sm + AKH + (ch*64 + nt*8 + g)*(KP*2);
#pragma unroll
            for (int kt = 0; kt < 2; kt++) {
                unsigned bh[2];
                bh[0] = *(const unsigned*)(kb + (kt*16 + kq)*2);
                bh[1] = *(const unsigned*)(kb + (kt*16 + kq)*2 + 16);
                mma16816(c[nt], qah[kt], bh);
            }
        }
        // ---- P = exp(s + bias) directly (m = 0), den partials ----
#pragma unroll
        for (int nt = 0; nt < 8; nt++) {
            float2 bb = *(const float2*)&sb[ch*64 + nt*8 + kq];
            c[nt][0] = __expf(c[nt][0] + bb.x);
            c[nt][1] = __expf(c[nt][1] + bb.y);
            c[nt][2] = __expf(c[nt][2] + bb.x);
            c[nt][3] = __expf(c[nt][3] + bb.y);
            d0 += c[nt][0] + c[nt][1];
            d1 += c[nt][2] + c[nt][3];
        }
        // ---- O += P_chunk * V_chunk (3-product hi/lo) ----
#pragma unroll
        for (int kt = 0; kt < 4; kt++) {
            unsigned ah[4], al[4];
            split2(c[2*kt][0],   c[2*kt][1],   ah[0], al[0]);
            split2(c[2*kt][2],   c[2*kt][3],   ah[1], al[1]);
            split2(c[2*kt+1][0], c[2*kt+1][1], ah[2], al[2]);
            split2(c[2*kt+1][2], c[2*kt+1][3], ah[3], al[3]);
#pragma unroll
            for (int nt = 0; nt < 4; nt++) {
                const char* vb = sm + (nt*8 + g)*(VP*2) + (ch*64 + kt*16 + kq)*2;
                unsigned bh[2], bl[2];
                bh[0] = *(const unsigned*)(vb + AVH);
                bh[1] = *(const unsigned*)(vb + AVH + 16);
                bl[0] = *(const unsigned*)(vb + AVL);
                bl[1] = *(const unsigned*)(vb + AVL + 16);
                mma16816(o[nt], ah, bh);
                mma16816(o[nt], al, bh);
                mma16816(o[nt], ah, bl);
            }
        }
    }

    // ---- reduce den partials across the quad ----
    d0 += __shfl_xor_sync(0xffffffffu, d0, 1);
    d0 += __shfl_xor_sync(0xffffffffu, d0, 2);
    d1 += __shfl_xor_sync(0xffffffffu, d1, 1);
    d1 += __shfl_xor_sync(0xffffffffu, d1, 2);

    // ---- epilogue: normalize, split, store ctx ----
    {
        float inv0 = 1.f / d0, inv1 = 1.f / d1;
        size_t orow = (size_t)bp*L_ + half*128 + wid*16;
#pragma unroll
        for (int nt = 0; nt < 4; nt++) {
            unsigned h0, l0, h1, l1;
            split2(o[nt][0]*inv0, o[nt][1]*inv0, h0, l0);
            split2(o[nt][2]*inv1, o[nt][3]*inv1, h1, l1);
            size_t i0 = (orow+g  )*D_ + h*HD_ + nt*8 + kq;
            size_t i1 = (orow+g+8)*D_ + h*HD_ + nt*8 + kq;
            *(unsigned*)&g_ctxh[i0] = h0;
            *(unsigned*)&g_ctxl[i0] = l0;
            *(unsigned*)&g_ctxh[i1] = h1;
            *(unsigned*)&g_ctxl[i1] = l1;
        }
    }
}

// ---------------------------------------------------------------------------
extern "C" void kernel_launch(void* const* d_in, const int* in_sizes, int n_in,
                              void* d_out, int out_size) {
    const float* ehr       = (const float*)d_in[0];
    const float* ehr_times = (const float*)d_in[1];
    const float* itv       = (const float*)d_in[2];
    const float* w1        = (const float*)d_in[3];
    const float* b1        = (const float*)d_in[4];
    const float* w2        = (const float*)d_in[5];
    const float* b2        = (const float*)d_in[6];
    const float* wq        = (const float*)d_in[7];
    const float* bq        = (const float*)d_in[8];
    const float* wk        = (const float*)d_in[9];
    const float* bk        = (const float*)d_in[10];
    const float* wv        = (const float*)d_in[11];
    const float* bv        = (const float*)d_in[12];
    const float* wo        = (const float*)d_in[13];
    const float* bo        = (const float*)d_in[14];
    float* out = (float*)d_out;

    __nv_bfloat16 *p_eh, *p_el, *p_kh, *p_vh, *p_vl, *p_qh;
    __nv_bfloat16 *p_hh, *p_hl, *p_w2qTh, *p_w2qTl;
    __nv_bfloat16 *p_ctxh, *p_ctxl, *p_woTh, *p_woTl;
    __nv_bfloat16 *p_wkT, *p_wvTh, *p_wvTl;
    float *p_bq2;
    cudaGetSymbolAddress((void**)&p_eh, g_eh);
    cudaGetSymbolAddress((void**)&p_el, g_el);
    cudaGetSymbolAddress((void**)&p_kh, g_kh);
    cudaGetSymbolAddress((void**)&p_vh, g_vh);
    cudaGetSymbolAddress((void**)&p_vl, g_vl);
    cudaGetSymbolAddress((void**)&p_qh, g_qh);
    cudaGetSymbolAddress((void**)&p_hh, g_hh);
    cudaGetSymbolAddress((void**)&p_hl, g_hl);
    cudaGetSymbolAddress((void**)&p_w2qTh, g_w2qTh);
    cudaGetSymbolAddress((void**)&p_w2qTl, g_w2qTl);
    cudaGetSymbolAddress((void**)&p_ctxh, g_ctxh);
    cudaGetSymbolAddress((void**)&p_ctxl, g_ctxl);
    cudaGetSymbolAddress((void**)&p_woTh, g_woTh);
    cudaGetSymbolAddress((void**)&p_woTl, g_woTl);
    cudaGetSymbolAddress((void**)&p_wkT, g_wkT);
    cudaGetSymbolAddress((void**)&p_wvTh, g_wvTh);
    cudaGetSymbolAddress((void**)&p_wvTl, g_wvTl);
    cudaGetSymbolAddress((void**)&p_bq2, g_bq2);

    fuse_w_kernel<<<DH_, D_>>>(w2, wq, b2, bq);
    prep_split_kernel<<<D_, D_>>>(wo, wk, wv);
    split_ehr_kernel<<<B_*L_, 256>>>(ehr);
    h_kernel<<<B_*P_*L_/32, 256>>>(ehr_times, itv, w1, b1);

    // K = ehr @ wk + bk  (single-product, single bf16 out)
    gemm_kernel<D_, false, 1><<<dim3(8, 2), 256>>>(
        p_eh, p_eh, p_wkT, p_wkT, bk, nullptr, p_kh, nullptr);
    // V = ehr @ wv + bv  (3-product, split hi/lo out)
    gemm_kernel<D_, true, 2><<<dim3(8, 2), 256>>>(
        p_eh, p_el, p_wvTh, p_wvTl, bv, nullptr, p_vh, p_vl);
    // q = h @ W2q' + bq2'  (3-product, single bf16 out)
    gemm_kernel<DH_, true, 1><<<dim3(256, 2), 256>>>(
        p_hh, p_hl, p_w2qTh, p_w2qTl, p_bq2, nullptr, p_qh, nullptr);

    cudaFuncSetAttribute(attn_kernel, cudaFuncAttributeMaxDynamicSharedMemorySize, ASM_TOT);
    attn_kernel<<<dim3(H_, 2, B_*P_), 256, ASM_TOT>>>(ehr_times, itv);

    // out = ctx @ wo + bo  (3-product, fp32 out)
    gemm_kernel<D_, true, 0><<<dim3(256, 2), 256>>>(
        p_ctxh, p_ctxl, p_woTh, p_woTl, bo, out, nullptr, nullptr);
}

// round 14
// speedup vs baseline: 1.4214x; 1.0745x over previous
#include <cuda_runtime.h>
#include <cuda_bf16.h>
#include <math.h>
#include <cstdint>

#define B_  4
#define L_  256
#define D_  256
#define P_  32
#define H_  8
#define HD_ 32
#define DH_ 128   // D/2

// ======================= mma.sync bf16 =====================================
__device__ __forceinline__ void mma16816(float* c, const unsigned* a, const unsigned* b) {
    asm volatile("mma.sync.aligned.m16n8k16.row.col.f32.bf16.bf16.f32 "
        "{%0,%1,%2,%3}, {%4,%5,%6,%7}, {%8,%9}, {%0,%1,%2,%3};"
        : "+f"(c[0]), "+f"(c[1]), "+f"(c[2]), "+f"(c[3])
        : "r"(a[0]), "r"(a[1]), "r"(a[2]), "r"(a[3]), "r"(b[0]), "r"(b[1]));
}
__device__ __forceinline__ unsigned pack_bf16x2(float x0, float x1) {
    __nv_bfloat162 t = __floats2bfloat162_rn(x0, x1);
    return *reinterpret_cast<unsigned*>(&t);
}
// fast split: hi = rn-rounded bf16 pair (1 cvt), lo from exact shift-expansion
__device__ __forceinline__ void split2(float x0, float x1, unsigned& whi, unsigned& wlo) {
    whi = pack_bf16x2(x0, x1);
    float h0 = __uint_as_float(whi << 16);
    float h1 = __uint_as_float(whi & 0xffff0000u);
    wlo = pack_bf16x2(x0 - h0, x1 - h1);
}
__device__ __forceinline__ void split1(float x, __nv_bfloat16& h, __nv_bfloat16& l) {
    h = __float2bfloat16(x);
    l = __float2bfloat16(x - __bfloat162float(h));
}

// ======================= scratch =========================================
__device__ __nv_bfloat16 g_eh[B_*L_*D_];        // ehr hi
__device__ __nv_bfloat16 g_el[B_*L_*D_];        // ehr lo
__device__ __nv_bfloat16 g_kh[B_*L_*D_];        // K single bf16
__device__ __nv_bfloat16 g_vth[B_*D_*L_];       // V^T hi [(b*D + c)][l]
__device__ __nv_bfloat16 g_vtl[B_*D_*L_];       // V^T lo
__device__ __nv_bfloat16 g_qh[B_*P_*L_*D_];     // q single bf16
__device__ __nv_bfloat16 g_ctxh[B_*P_*L_*D_];
__device__ __nv_bfloat16 g_ctxl[B_*P_*L_*D_];
__device__ __nv_bfloat16 g_hh[B_*P_*L_*DH_];
__device__ __nv_bfloat16 g_hl[B_*P_*L_*DH_];
__device__ __nv_bfloat16 g_woTh[D_*D_];         // [n][k]
__device__ __nv_bfloat16 g_woTl[D_*D_];
__device__ __nv_bfloat16 g_wkT[D_*D_];          // [n][k] single bf16
__device__ __nv_bfloat16 g_wvTh[D_*D_];         // [n][k]
__device__ __nv_bfloat16 g_wvTl[D_*D_];
__device__ __nv_bfloat16 g_w2qTh[D_*DH_];       // [n][k], scale folded
__device__ __nv_bfloat16 g_w2qTl[D_*DH_];
__device__ float g_W2q[DH_*D_];
__device__ float g_bq2[D_];                     // scale folded

// ---------------------------------------------------------------------------
// Kernel 1: W2q = w2 @ wq, bq2 = scale*(b2 @ wq + bq)
// ---------------------------------------------------------------------------
__global__ void fuse_w_kernel(const float* __restrict__ w2, const float* __restrict__ wq,
                              const float* __restrict__ b2, const float* __restrict__ bq) {
    int j = blockIdx.x, c = threadIdx.x;
    float acc = 0.f;
    for (int k = 0; k < D_; k++) acc = fmaf(w2[j*D_+k], wq[k*D_+c], acc);
    g_W2q[j*D_+c] = acc;
    if (j == 0) {
        float a = 0.f;
        for (int k = 0; k < D_; k++) a = fmaf(b2[k], wq[k*D_+c], a);
        g_bq2[c] = 0.17677669529663687f * (a + bq[c]);
    }
}

// ---------------------------------------------------------------------------
// Kernel 1b: transpose+split weights
// ---------------------------------------------------------------------------
__global__ void prep_split_kernel(const float* __restrict__ wo,
                                  const float* __restrict__ wk,
                                  const float* __restrict__ wv) {
    int n = blockIdx.x, k = threadIdx.x;
    __nv_bfloat16 h, l;
    split1(wo[k*D_ + n], h, l);
    g_woTh[n*D_ + k] = h;
    g_woTl[n*D_ + k] = l;
    g_wkT[n*D_ + k] = __float2bfloat16(wk[k*D_ + n]);
    split1(wv[k*D_ + n], h, l);
    g_wvTh[n*D_ + k] = h;
    g_wvTl[n*D_ + k] = l;
    if (k < DH_) {
        split1(0.17677669529663687f * g_W2q[k*D_ + n], h, l);
        g_w2qTh[n*DH_ + k] = h;
        g_w2qTl[n*DH_ + k] = l;
    }
}

// ---------------------------------------------------------------------------
// Kernel 1c: split ehr into hi/lo bf16
// ---------------------------------------------------------------------------
__global__ void split_ehr_kernel(const float* __restrict__ ehr) {
    int i = blockIdx.x * 256 + threadIdx.x;
    __nv_bfloat16 h, l;
    split1(ehr[i], h, l);
    g_eh[i] = h;
    g_el[i] = l;
}

// ---------------------------------------------------------------------------
// Kernel 3: time features -> MLP -> gelu -> h (split bf16)
// ---------------------------------------------------------------------------
__global__ void h_kernel(const float* __restrict__ ehr_times, const float* __restrict__ itv,
                         const float* __restrict__ w1, const float* __restrict__ b1) {
    __shared__ float3 stf[32];
    int tid = threadIdx.x;
    int g0 = blockIdx.x * 32;
    int b  = g0 / (P_*L_);
    int p  = (g0 / L_) % P_;
    int l0 = g0 % L_;
    if (tid < 32) {
        float t = ehr_times[b*L_ + l0 + tid];
        float s = itv[(b*P_+p)*2 + 0];
        float e = itv[(b*P_+p)*2 + 1];
        float ds = t - s, de = e - t;
        float x  = ds * de;
        float sg = 1.f / (1.f + expf(-x));
        stf[tid] = make_float3(ds, de, sg);
    }
    __syncthreads();
    for (int i = tid; i < 32*DH_; i += 256) {
        int r = i >> 7, j = i & 127;
        float3 tf = stf[r];
        float z = tf.x*w1[j] + tf.y*w1[DH_+j] + tf.z*w1[2*DH_+j] + b1[j];
        float v = 0.5f * z * (1.f + erff(z * 0.70710678118654752f));
        __nv_bfloat16 h, l;
        split1(v, h, l);
        g_hh[(size_t)g0*DH_ + i] = h;
        g_hl[(size_t)g0*DH_ + i] = l;
    }
}

// ---------------------------------------------------------------------------
// Generic bf16 GEMM. PROD3: hi/lo 3-product.
// OM: 0 fp32, 1 single bf16, 2 split bf16, 3 split bf16 TRANSPOSED [(b*D+n)][l]
// ---------------------------------------------------------------------------
template<int K, bool PROD3, int OM>
__global__ void __launch_bounds__(256)
gemm_kernel(const __nv_bfloat16* __restrict__ Ah, const __nv_bfloat16* __restrict__ Al,
            const __nv_bfloat16* __restrict__ BTh, const __nv_bfloat16* __restrict__ BTl,
            const float* __restrict__ bias,
            float* __restrict__ outF,
            __nv_bfloat16* __restrict__ outH, __nv_bfloat16* __restrict__ outL) {
    __shared__ __nv_bfloat16 sAh[128*40], sAl[128*40], sBh[128*40], sBl[128*40];
    int tid = threadIdx.x, wid = tid >> 5, lane = tid & 31;
    int g = lane >> 2, kq = (lane & 3) * 2;
    int wm = wid & 3, wn = wid >> 2;
    int m0 = blockIdx.x * 128, n0 = blockIdx.y * 128;

    float c[2][8][4];
#pragma unroll
    for (int nt = 0; nt < 8; nt++) {
        float2 bb = *(const float2*)&bias[n0 + wn*64 + nt*8 + kq];
#pragma unroll
        for (int mt = 0; mt < 2; mt++) {
            c[mt][nt][0] = bb.x; c[mt][nt][1] = bb.y;
            c[mt][nt][2] = bb.x; c[mt][nt][3] = bb.y;
        }
    }

    for (int kc = 0; kc < K; kc += 32) {
        for (int idx = tid; idx < 1024; idx += 256) {
            int r = idx >> 3, c4 = (idx & 7) * 4;
            *(uint2*)&sAh[r*40 + c4] = *(const uint2*)&Ah[(size_t)(m0+r)*K + kc + c4];
            *(uint2*)&sBh[r*40 + c4] = *(const uint2*)&BTh[(size_t)(n0+r)*K + kc + c4];
            if (PROD3) {
                *(uint2*)&sAl[r*40 + c4] = *(const uint2*)&Al[(size_t)(m0+r)*K + kc + c4];
                *(uint2*)&sBl[r*40 + c4] = *(const uint2*)&BTl[(size_t)(n0+r)*K + kc + c4];
            }
        }
        __syncthreads();
#pragma unroll
        for (int kt = 0; kt < 2; kt++) {
            unsigned ah[2][4], al[2][4];
#pragma unroll
            for (int mt = 0; mt < 2; mt++) {
                int rb = wm*32 + mt*16;
                ah[mt][0] = *(const unsigned*)&sAh[(rb+g  )*40 + kt*16 + kq];
                ah[mt][1] = *(const unsigned*)&sAh[(rb+g+8)*40 + kt*16 + kq];
                ah[mt][2] = *(const unsigned*)&sAh[(rb+g  )*40 + kt*16 + kq + 8];
                ah[mt][3] = *(const unsigned*)&sAh[(rb+g+8)*40 + kt*16 + kq + 8];
                if (PROD3) {
                    al[mt][0] = *(const unsigned*)&sAl[(rb+g  )*40 + kt*16 + kq];
                    al[mt][1] = *(const unsigned*)&sAl[(rb+g+8)*40 + kt*16 + kq];
                    al[mt][2] = *(const unsigned*)&sAl[(rb+g  )*40 + kt*16 + kq + 8];
                    al[mt][3] = *(const unsigned*)&sAl[(rb+g+8)*40 + kt*16 + kq + 8];
                }
            }
#pragma unroll
            for (int nt = 0; nt < 8; nt++) {
                int rn = wn*64 + nt*8 + g;
                unsigned bh[2], bl[2];
                bh[0] = *(const unsigned*)&sBh[rn*40 + kt*16 + kq];
                bh[1] = *(const unsigned*)&sBh[rn*40 + kt*16 + kq + 8];
                if (PROD3) {
                    bl[0] = *(const unsigned*)&sBl[rn*40 + kt*16 + kq];
                    bl[1] = *(const unsigned*)&sBl[rn*40 + kt*16 + kq + 8];
                }
#pragma unroll
                for (int mt = 0; mt < 2; mt++) {
                    mma16816(c[mt][nt], ah[mt], bh);
                    if (PROD3) {
                        mma16816(c[mt][nt], al[mt], bh);
                        mma16816(c[mt][nt], ah[mt], bl);
                    }
                }
            }
        }
        __syncthreads();
    }

#pragma unroll
    for (int mt = 0; mt < 2; mt++) {
        int r0 = m0 + wm*32 + mt*16 + g;
#pragma unroll
        for (int nt = 0; nt < 8; nt++) {
            int col = n0 + wn*64 + nt*8 + kq;
            if (OM == 0) {
                *(float2*)&outF[(size_t)r0*D_ + col] = make_float2(c[mt][nt][0], c[mt][nt][1]);
                *(float2*)&outF[(size_t)(r0+8)*D_ + col] = make_float2(c[mt][nt][2], c[mt][nt][3]);
            } else if (OM == 1) {
                *(unsigned*)&outH[(size_t)r0*D_ + col]     = pack_bf16x2(c[mt][nt][0], c[mt][nt][1]);
                *(unsigned*)&outH[(size_t)(r0+8)*D_ + col] = pack_bf16x2(c[mt][nt][2], c[mt][nt][3]);
            } else if (OM == 2) {
                unsigned h0, l0, h1, l1;
                split2(c[mt][nt][0], c[mt][nt][1], h0, l0);
                split2(c[mt][nt][2], c[mt][nt][3], h1, l1);
                *(unsigned*)&outH[(size_t)r0*D_ + col] = h0;
                *(unsigned*)&outL[(size_t)r0*D_ + col] = l0;
                *(unsigned*)&outH[(size_t)(r0+8)*D_ + col] = h1;
                *(unsigned*)&outL[(size_t)(r0+8)*D_ + col] = l1;
            } else {
                // transposed split: out[(b*D + col)*L + l], rows r0 and r0+8
                unsigned h0, l0, h1, l1;
                split2(c[mt][nt][0], c[mt][nt][1], h0, l0);
                split2(c[mt][nt][2], c[mt][nt][3], h1, l1);
                int b0 = r0 / L_,  lA = r0 % L_;
                int b1i = (r0+8) / L_, lB = (r0+8) % L_;   // same b (L multiple of 128)
                size_t t0 = ((size_t)b0*D_ + col)*L_ + lA;
                size_t t1 = ((size_t)b1i*D_ + col)*L_ + lB;
                *(unsigned short*)&outH[t0]      = (unsigned short)h0;
                *(unsigned short*)&outH[t0 + L_] = (unsigned short)(h0 >> 16);
                *(unsigned short*)&outL[t0]      = (unsigned short)l0;
                *(unsigned short*)&outL[t0 + L_] = (unsigned short)(l0 >> 16);
                *(unsigned short*)&outH[t1]      = (unsigned short)h1;
                *(unsigned short*)&outH[t1 + L_] = (unsigned short)(h1 >> 16);
                *(unsigned short*)&outL[t1]      = (unsigned short)l1;
                *(unsigned short*)&outL[t1 + L_] = (unsigned short)(l1 >> 16);
            }
        }
    }
}

// ---------------------------------------------------------------------------
// Kernel 4: flash attention, no-max softmax, V^T pre-transposed (vector fill)
// ---------------------------------------------------------------------------
#define AKH 0                          // K bf16 [256][40] = 20480 B
#define AVH 20480                      // V^T hi [32][264] = 16896 B
#define AVL 37376                      // V^T lo
#define ABI 54272                      // 256 f32
#define ASM_TOT 55296
#define KP  40
#define VP  264

__global__ void __launch_bounds__(256, 2)
attn_kernel(const float* __restrict__ ehr_times, const float* __restrict__ itv) {
    extern __shared__ char sm[];
    int tid = threadIdx.x;
    int wid = tid >> 5, lane = tid & 31;
    int g  = lane >> 2;
    int kq = (lane & 3) * 2;
    int h    = blockIdx.x;
    int half = blockIdx.y;
    int bp   = blockIdx.z;
    int b = bp >> 5;

    {
        const __nv_bfloat16* kh = g_kh + (size_t)(b*L_)*D_ + h*HD_;
        for (int idx = tid; idx < 2048; idx += 256) {
            int r = idx >> 3, c4 = (idx & 7) * 4;
            *(uint2*)(sm + AKH + r*(KP*2) + c4*2) = *(const uint2*)(kh + r*D_ + c4);
        }
    }
    {
        const __nv_bfloat16* vh = g_vth + (size_t)(b*D_ + h*HD_)*L_;
        const __nv_bfloat16* vl = g_vtl + (size_t)(b*D_ + h*HD_)*L_;
        for (int idx = tid; idx < 1024; idx += 256) {
            int hd = idx >> 5, c8 = (idx & 31) * 8;
            *(uint4*)(sm + AVH + hd*(VP*2) + c8*2) = *(const uint4*)(vh + hd*L_ + c8);
            *(uint4*)(sm + AVL + hd*(VP*2) + c8*2) = *(const uint4*)(vl + hd*L_ + c8);
        }
    }
    {
        float s = itv[bp*2 + 0];
        float e = itv[bp*2 + 1];
        float ctr = 0.5f*(s+e);
        float t = ehr_times[b*L_ + tid];
        ((float*)(sm + ABI))[tid] = (t >= s && t <= e) ? -fabsf(t - ctr) : -1e30f;
    }

    unsigned qah[2][4];
    {
        size_t qrow = (size_t)bp*L_ + half*128 + wid*16;
#pragma unroll
        for (int kt = 0; kt < 2; kt++) {
            size_t base = (qrow + g)*D_ + h*HD_ + kt*16 + kq;
            qah[kt][0] = *(const unsigned*)(g_qh + base);
            qah[kt][1] = *(const unsigned*)(g_qh + base + 8*D_);
            qah[kt][2] = *(const unsigned*)(g_qh + base + 8);
            qah[kt][3] = *(const unsigned*)(g_qh + base + 8*D_ + 8);
        }
    }
    __syncthreads();

    const float* sb = (const float*)(sm + ABI);
    float d0 = 0.f, d1 = 0.f;
    float o[4][4];
#pragma unroll
    for (int nt = 0; nt < 4; nt++) { o[nt][0]=0.f; o[nt][1]=0.f; o[nt][2]=0.f; o[nt][3]=0.f; }

#pragma unroll 1
    for (int ch = 0; ch < 4; ch++) {
        // ---- S chunk = Q K^T (single bf16 product) ----
        float c[8][4];
#pragma unroll
        for (int nt = 0; nt < 8; nt++) { c[nt][0]=0.f; c[nt][1]=0.f; c[nt][2]=0.f; c[nt][3]=0.f; }
#pragma unroll
        for (int nt = 0; nt < 8; nt++) {
            const char* kb = sm + AKH + (ch*64 + nt*8 + g)*(KP*2);
#pragma unroll
            for (int kt = 0; kt < 2; kt++) {
                unsigned bh[2];
                bh[0] = *(const unsigned*)(kb + (kt*16 + kq)*2);
                bh[1] = *(const unsigned*)(kb + (kt*16 + kq)*2 + 16);
                mma16816(c[nt], qah[kt], bh);
            }
        }
        // ---- P = exp(s + bias) directly (m = 0), den partials ----
#pragma unroll
        for (int nt = 0; nt < 8; nt++) {
            float2 bb = *(const float2*)&sb[ch*64 + nt*8 + kq];
            c[nt][0] = __expf(c[nt][0] + bb.x);
            c[nt][1] = __expf(c[nt][1] + bb.y);
            c[nt][2] = __expf(c[nt][2] + bb.x);
            c[nt][3] = __expf(c[nt][3] + bb.y);
            d0 += c[nt][0] + c[nt][1];
            d1 += c[nt][2] + c[nt][3];
        }
        // ---- O += P_chunk * V_chunk (3-product hi/lo) ----
#pragma unroll
        for (int kt = 0; kt < 4; kt++) {
            unsigned ah[4], al[4];
            split2(c[2*kt][0],   c[2*kt][1],   ah[0], al[0]);
            split2(c[2*kt][2],   c[2*kt][3],   ah[1], al[1]);
            split2(c[2*kt+1][0], c[2*kt+1][1], ah[2], al[2]);
            split2(c[2*kt+1][2], c[2*kt+1][3], ah[3], al[3]);
#pragma unroll
            for (int nt = 0; nt < 4; nt++) {
                const char* vb = sm + (nt*8 + g)*(VP*2) + (ch*64 + kt*16 + kq)*2;
                unsigned bh[2], bl[2];
                bh[0] = *(const unsigned*)(vb + AVH);
                bh[1] = *(const unsigned*)(vb + AVH + 16);
                bl[0] = *(const unsigned*)(vb + AVL);
                bl[1] = *(const unsigned*)(vb + AVL + 16);
                mma16816(o[nt], ah, bh);
                mma16816(o[nt], al, bh);
                mma16816(o[nt], ah, bl);
            }
        }
    }

    // ---- reduce den partials across the quad ----
    d0 += __shfl_xor_sync(0xffffffffu, d0, 1);
    d0 += __shfl_xor_sync(0xffffffffu, d0, 2);
    d1 += __shfl_xor_sync(0xffffffffu, d1, 1);
    d1 += __shfl_xor_sync(0xffffffffu, d1, 2);

    // ---- epilogue: normalize, split, store ctx ----
    {
        float inv0 = 1.f / d0, inv1 = 1.f / d1;
        size_t orow = (size_t)bp*L_ + half*128 + wid*16;
#pragma unroll
        for (int nt = 0; nt < 4; nt++) {
            unsigned h0, l0, h1, l1;
            split2(o[nt][0]*inv0, o[nt][1]*inv0, h0, l0);
            split2(o[nt][2]*inv1, o[nt][3]*inv1, h1, l1);
            size_t i0 = (orow+g  )*D_ + h*HD_ + nt*8 + kq;
            size_t i1 = (orow+g+8)*D_ + h*HD_ + nt*8 + kq;
            *(unsigned*)&g_ctxh[i0] = h0;
            *(unsigned*)&g_ctxl[i0] = l0;
            *(unsigned*)&g_ctxh[i1] = h1;
            *(unsigned*)&g_ctxl[i1] = l1;
        }
    }
}

// ---------------------------------------------------------------------------
extern "C" void kernel_launch(void* const* d_in, const int* in_sizes, int n_in,
                              void* d_out, int out_size) {
    const float* ehr       = (const float*)d_in[0];
    const float* ehr_times = (const float*)d_in[1];
    const float* itv       = (const float*)d_in[2];
    const float* w1        = (const float*)d_in[3];
    const float* b1        = (const float*)d_in[4];
    const float* w2        = (const float*)d_in[5];
    const float* b2        = (const float*)d_in[6];
    const float* wq        = (const float*)d_in[7];
    const float* bq        = (const float*)d_in[8];
    const float* wk        = (const float*)d_in[9];
    const float* bk        = (const float*)d_in[10];
    const float* wv        = (const float*)d_in[11];
    const float* bv        = (const float*)d_in[12];
    const float* wo        = (const float*)d_in[13];
    const float* bo        = (const float*)d_in[14];
    float* out = (float*)d_out;

    __nv_bfloat16 *p_eh, *p_el, *p_kh, *p_vth, *p_vtl, *p_qh;
    __nv_bfloat16 *p_hh, *p_hl, *p_w2qTh, *p_w2qTl;
    __nv_bfloat16 *p_ctxh, *p_ctxl, *p_woTh, *p_woTl;
    __nv_bfloat16 *p_wkT, *p_wvTh, *p_wvTl;
    float *p_bq2;
    cudaGetSymbolAddress((void**)&p_eh, g_eh);
    cudaGetSymbolAddress((void**)&p_el, g_el);
    cudaGetSymbolAddress((void**)&p_kh, g_kh);
    cudaGetSymbolAddress((void**)&p_vth, g_vth);
    cudaGetSymbolAddress((void**)&p_vtl, g_vtl);
    cudaGetSymbolAddress((void**)&p_qh, g_qh);
    cudaGetSymbolAddress((void**)&p_hh, g_hh);
    cudaGetSymbolAddress((void**)&p_hl, g_hl);
    cudaGetSymbolAddress((void**)&p_w2qTh, g_w2qTh);
    cudaGetSymbolAddress((void**)&p_w2qTl, g_w2qTl);
    cudaGetSymbolAddress((void**)&p_ctxh, g_ctxh);
    cudaGetSymbolAddress((void**)&p_ctxl, g_ctxl);
    cudaGetSymbolAddress((void**)&p_woTh, g_woTh);
    cudaGetSymbolAddress((void**)&p_woTl, g_woTl);
    cudaGetSymbolAddress((void**)&p_wkT, g_wkT);
    cudaGetSymbolAddress((void**)&p_wvTh, g_wvTh);
    cudaGetSymbolAddress((void**)&p_wvTl, g_wvTl);
    cudaGetSymbolAddress((void**)&p_bq2, g_bq2);

    fuse_w_kernel<<<DH_, D_>>>(w2, wq, b2, bq);
    prep_split_kernel<<<D_, D_>>>(wo, wk, wv);
    split_ehr_kernel<<<B_*L_, 256>>>(ehr);
    h_kernel<<<B_*P_*L_/32, 256>>>(ehr_times, itv, w1, b1);

    // K = ehr @ wk + bk  (single-product, single bf16 out)
    gemm_kernel<D_, false, 1><<<dim3(8, 2), 256>>>(
        p_eh, p_eh, p_wkT, p_wkT, bk, nullptr, p_kh, nullptr);
    // V = ehr @ wv + bv  (3-product, TRANSPOSED split hi/lo out)
    gemm_kernel<D_, true, 3><<<dim3(8, 2), 256>>>(
        p_eh, p_el, p_wvTh, p_wvTl, bv, nullptr, p_vth, p_vtl);
    // q = h @ W2q' + bq2'  (3-product, single bf16 out)
    gemm_kernel<DH_, true, 1><<<dim3(256, 2), 256>>>(
        p_hh, p_hl, p_w2qTh, p_w2qTl, p_bq2, nullptr, p_qh, nullptr);

    cudaFuncSetAttribute(attn_kernel, cudaFuncAttributeMaxDynamicSharedMemorySize, ASM_TOT);
    attn_kernel<<<dim3(H_, 2, B_*P_), 256, ASM_TOT>>>(ehr_times, itv);

    // out = ctx @ wo + bo  (3-product, fp32 out)
    gemm_kernel<D_, true, 0><<<dim3(256, 2), 256>>>(
        p_ctxh, p_ctxl, p_woTh, p_woTl, bo, out, nullptr, nullptr);
}